// round 11
// baseline (speedup 1.0000x reference)
#include <cuda_runtime.h>
#include <cuda_fp16.h>
#include <stdint.h>

// ---------------------------------------------------------------------------
// Scratch for fp16-converted operands (W padded 256 rows for OOB-safe cp.async)
// ---------------------------------------------------------------------------
#define H_CAP 1024
#define V_CAP 50000
#define M_CAP 1024
__device__ __half g_Wh[(size_t)(V_CAP + 256) * H_CAP];   // ~100.5 MB
__device__ __half g_Ah[(size_t)M_CAP * H_CAP];           // 2 MB

// ---------------------------------------------------------------------------
// Tiling: CTA 128x256, 8 warps (2m x 4n), warp tile 64x64, 256 threads
// KC=128 as 2 sub-tiles of 64 cols (128B rows, SW128). Persistent CTAs.
// Loader strip-mined: 24 cp.async/thread/chunk issued as 8 slices of 3,
// one slice per k-step (uniform MIO pressure across the whole chunk).
// ---------------------------------------------------------------------------
#define TM 128
#define TN 256
#define KC 128
#define NTH 256
#define NCH_K 8          // H/KC

#define SM_RED   0                      // 16 doubles
#define SM_PIPE  4096
#define ASUB     (TM * 128)             // 16384 B
#define BSUB     (TN * 128)             // 32768 B
#define ASTAGE   (2 * ASUB)             // 32768 B
#define BSTAGE   (2 * BSUB)             // 65536 B
#define STAGEB   (ASTAGE + BSTAGE)      // 98304 B
#define SMEM_TOTAL (SM_PIPE + 2 * STAGEB)   // 200704 B (1 CTA/SM)

// ---------------------------------------------------------------------------
// PTX helpers (sm_80-baseline features: safe under compute_103 virtual arch)
// ---------------------------------------------------------------------------
__device__ __forceinline__ uint32_t smem_u32(const void* p) {
    uint32_t a;
    asm("{ .reg .u64 t; cvta.to.shared.u64 t, %1; cvt.u32.u64 %0, t; }" : "=r"(a) : "l"(p));
    return a;
}
__device__ __forceinline__ void cp16(uint32_t dst, const void* src, uint32_t srcbytes) {
    asm volatile("cp.async.cg.shared.global [%0], [%1], 16, %2;"
                 :: "r"(dst), "l"(src), "r"(srcbytes));
}
#define CP_COMMIT() asm volatile("cp.async.commit_group;" ::: "memory")
#define CP_WAIT(n)  asm volatile("cp.async.wait_group %0;" :: "n"(n) : "memory")

__device__ __forceinline__ void ldsm_x4(uint32_t* r, uint32_t addr) {
    asm volatile("ldmatrix.sync.aligned.m8n8.x4.shared.b16 {%0,%1,%2,%3}, [%4];"
                 : "=r"(r[0]), "=r"(r[1]), "=r"(r[2]), "=r"(r[3]) : "r"(addr));
}
__device__ __forceinline__ void mma16816(float* c, const uint32_t* a, uint32_t b0, uint32_t b1) {
    asm volatile(
        "mma.sync.aligned.m16n8k16.row.col.f32.f16.f16.f32 "
        "{%0,%1,%2,%3}, {%4,%5,%6,%7}, {%8,%9}, {%0,%1,%2,%3};"
        : "+f"(c[0]), "+f"(c[1]), "+f"(c[2]), "+f"(c[3])
        : "r"(a[0]), "r"(a[1]), "r"(a[2]), "r"(a[3]), "r"(b0), "r"(b1));
}
__device__ __forceinline__ void stcs2(float* p, float x, float y) {
    asm volatile("st.global.cs.v2.f32 [%0], {%1, %2};" :: "l"(p), "f"(x), "f"(y) : "memory");
}

// log1p(t) on [0,1], |err| < 3e-8 (A&S 4.1.44) — FMA-pipe only
__device__ __forceinline__ float log1p_poly(float t) {
    float p = -0.0064535442f;
    p = fmaf(p, t,  0.0360884937f);
    p = fmaf(p, t, -0.0953293897f);
    p = fmaf(p, t,  0.1676540711f);
    p = fmaf(p, t, -0.2407338084f);
    p = fmaf(p, t,  0.3317990258f);
    p = fmaf(p, t, -0.4998741238f);
    p = fmaf(p, t,  0.9999964239f);
    return p * t;
}

// ---------------------------------------------------------------------------
// Global loss accumulators
// ---------------------------------------------------------------------------
__device__ double g_sum_base;
__device__ double g_sum_gather;

__global__ void zero_acc_kernel() { g_sum_base = 0.0; g_sum_gather = 0.0; }

// ---------------------------------------------------------------------------
// fp32 -> fp16 conversion (8 floats per thread)
// ---------------------------------------------------------------------------
__global__ void cvt_kernel(const float* __restrict__ s, __half* __restrict__ d, int n8) {
    int i = blockIdx.x * blockDim.x + threadIdx.x;
    if (i < n8) {
        float4 v0 = reinterpret_cast<const float4*>(s)[2 * i + 0];
        float4 v1 = reinterpret_cast<const float4*>(s)[2 * i + 1];
        __half2 h0 = __floats2half2_rn(v0.x, v0.y);
        __half2 h1 = __floats2half2_rn(v0.z, v0.w);
        __half2 h2 = __floats2half2_rn(v1.x, v1.y);
        __half2 h3 = __floats2half2_rn(v1.z, v1.w);
        __half2* dp = reinterpret_cast<__half2*>(d) + 4 * i;
        dp[0] = h0; dp[1] = h1; dp[2] = h2; dp[3] = h3;
    }
}

// ---------------------------------------------------------------------------
// Persistent fused GEMM + BCE-loss kernel
//   logits[M,V] = A[M,H] @ W[V,H]^T  (fp16 in, fp32 accumulate)
// ---------------------------------------------------------------------------
__global__ void __launch_bounds__(NTH, 1)
spel_gemm_kernel(const long long* __restrict__ labels,
                 const float* __restrict__ attn_mask,
                 float* __restrict__ out,
                 int M, int H, int V, int write_logits,
                 int ntiles, int ntm) {
    extern __shared__ char smem[];
    const uint32_t sbase = smem_u32(smem);
    const int tid  = threadIdx.x;
    const int wid  = tid >> 5;
    const int lane = tid & 31;
    const int warp_m = wid >> 2;          // 0..1
    const int warp_n = wid & 3;           // 0..3

    const __half* __restrict__ Ah = g_Ah;
    const __half* __restrict__ Wh = g_Wh;
    const size_t rstep = (size_t)32 * H;  // 32-row pointer stride

    int t = blockIdx.x;
    if (t >= ntiles) return;

    float acc[4][8][4];
    #pragma unroll
    for (int i = 0; i < 4; ++i)
        #pragma unroll
        for (int j = 0; j < 8; ++j)
            #pragma unroll
            for (int k = 0; k < 4; ++k) acc[i][j][k] = 0.f;

    // ---- loader geometry ----
    const int seg = tid & 7;
    const int r0  = tid >> 3;                               // 0..31
    const uint32_t maskR = ((uint32_t)r0 * 16u) & 0x70u;
    const uint32_t dstR  = (((uint32_t)(r0 * 128 + seg * 16)) ^ maskR);

    // one cp.async entry e (0..23): e<8 -> A (sub=e>>2, jj=e&3); else B (eb=e-8)
    auto load_entry = [&](uint32_t dA, const __half* pA, const __half* pB,
                          int n0c, int e) {
        if (e < 8) {
            int sub = e >> 2, jj = e & 3;
            cp16(dA + sub * ASUB + jj * 4096u,
                 pA + sub * 64 + (size_t)jj * rstep, 16u);
        } else {
            int eb = e - 8;
            int sub = eb >> 3, jj = eb & 7;
            int gn = n0c + r0 + jj * 32;
            cp16(dA + ASTAGE + sub * BSUB + jj * 4096u,
                 pB + sub * 64 + (size_t)jj * rstep, (gn < V) ? 16u : 0u);
        }
    };

    // full chunk load (prologue only)
    auto load_chunk_full = [&](int st, int m0c, int n0c, int c) {
        const int k0 = c * KC;
        const uint32_t dA = sbase + SM_PIPE + st * STAGEB + dstR;
        const __half* pA = Ah + (size_t)(m0c + r0) * H + k0 + seg * 8;
        const __half* pB = Wh + (size_t)(n0c + r0) * H + k0 + seg * 8;
        #pragma unroll
        for (int e = 0; e < 24; ++e) load_entry(dA, pA, pB, n0c, e);
    };

    // ---- per-warp constant swizzled ldmatrix offsets ----
    const int a_row  = warp_m * 64 + (lane & 15);
    const int b_row0 = warp_n * 64 + (lane & 7) + ((lane & 16) ? 8 : 0);
    const uint32_t khiA2 = (lane & 16) ? 16u : 0u;
    const uint32_t khiB2 = (lane & 8)  ? 16u : 0u;
    uint32_t offA[4], offB[4];
    #pragma unroll
    for (int mt = 0; mt < 4; ++mt) {
        uint32_t R = (uint32_t)(a_row + mt * 16) * 128u;
        offA[mt] = R ^ ((R >> 3) & 0x70u) ^ khiA2;
    }
    #pragma unroll
    for (int h = 0; h < 4; ++h) {
        uint32_t R = (uint32_t)(b_row0 + h * 16) * 128u;
        offB[h] = R ^ ((R >> 3) & 0x70u) ^ khiB2;
    }

    // ---- persistent pipeline over (tile, chunk) ----
    int m0 = (t % ntm) * TM, n0 = (t / ntm) * TN;
    load_chunk_full(0, m0, n0, 0);
    CP_COMMIT();
    int s = 0;
    float s_base = 0.f, s_g = 0.f;
    const int gq = lane >> 2;
    const int q  = (lane & 3) * 2;

    for (;;) {
        #pragma unroll 1
        for (int c = 0; c < NCH_K; ++c) {
            // next-chunk coordinates (cross-tile prefetch)
            int nm0 = m0, nn0 = n0, nc = c + 1;
            bool have_next = true;
            if (nc == NCH_K) {
                int tn = t + gridDim.x;
                if (tn < ntiles) { nm0 = (tn % ntm) * TM; nn0 = (tn / ntm) * TN; nc = 0; }
                else have_next = false;
            }
            const uint32_t dAn = sbase + SM_PIPE + (s ^ 1) * STAGEB + dstR;
            const __half* pAn = Ah + (size_t)(nm0 + r0) * H + nc * KC + seg * 8;
            const __half* pBn = Wh + (size_t)(nn0 + r0) * H + nc * KC + seg * 8;

            CP_WAIT(0);           // chunk c (committed last iteration) done
            __syncthreads();      // visible to all warps; stage s^1 free

            const uint32_t sA = sbase + SM_PIPE + s * STAGEB;
            const uint32_t sB = sA + ASTAGE;

            #pragma unroll
            for (int ks = 0; ks < KC / 16; ++ks) {
                // strip-mined loader: one slice of 3 entries per k-step
                if (have_next) {
                    #pragma unroll
                    for (int i = 0; i < 3; ++i)
                        load_entry(dAn, pAn, pBn, nn0, ks * 3 + i);
                }
                const uint32_t kx = (uint32_t)(ks & 3) * 32u;
                const uint32_t aO = sA + (uint32_t)(ks >> 2) * ASUB;
                const uint32_t bO = sB + (uint32_t)(ks >> 2) * BSUB;
                uint32_t af[4][4], bf[4][4];
                #pragma unroll
                for (int mt = 0; mt < 4; ++mt) ldsm_x4(af[mt], aO + (offA[mt] ^ kx));
                #pragma unroll
                for (int h = 0; h < 4; ++h)    ldsm_x4(bf[h],  bO + (offB[h] ^ kx));
                #pragma unroll
                for (int mt = 0; mt < 4; ++mt) {
                    #pragma unroll
                    for (int nt = 0; nt < 8; ++nt) {
                        mma16816(acc[mt][nt], af[mt],
                                 bf[nt >> 1][(nt & 1) * 2 + 0],
                                 bf[nt >> 1][(nt & 1) * 2 + 1]);
                    }
                }
            }
            if (have_next) CP_COMMIT();
            s ^= 1;
        }

        // ---- epilogue (no syncs; overlaps next tile's in-flight loads) ----
        // acc[] indices are all compile-time (dynamic would spill to local).
        {
            const int colbase = n0 + warp_n * 64;
            #pragma unroll
            for (int mt = 0; mt < 4; ++mt) {
                #pragma unroll
                for (int half = 0; half < 2; ++half) {
                    const int r = warp_m * 64 + mt * 16 + gq + half * 8;
                    const int gm = m0 + r;
                    if (gm < M) {
                        const float mk = attn_mask[gm];
                        const long long lb = labels[gm];
                        float* orow = out + (size_t)gm * V;
                        float rowsum = 0.f;
                        #pragma unroll
                        for (int nt = 0; nt < 8; ++nt) {
                            const int gn = colbase + nt * 8 + q;
                            if (gn < V) {
                                const float x0 = acc[mt][nt][half * 2 + 0];
                                const float x1 = acc[mt][nt][half * 2 + 1];
                                if (write_logits) stcs2(orow + gn, x0, x1);
                                rowsum += fmaxf(x0, 0.f) + log1p_poly(__expf(-fabsf(x0)));
                                rowsum += fmaxf(x1, 0.f) + log1p_poly(__expf(-fabsf(x1)));
                                if (mk > 0.f) {
                                    if (lb == (long long)gn)          s_g += x0 * mk;
                                    else if (lb == (long long)gn + 1) s_g += x1 * mk;
                                }
                            }
                        }
                        s_base += rowsum * mk;
                    }
                }
            }
            #pragma unroll
            for (int i = 0; i < 4; ++i)
                #pragma unroll
                for (int j = 0; j < 8; ++j)
                    #pragma unroll
                    for (int k = 0; k < 4; ++k) acc[i][j][k] = 0.f;
        }

        t += gridDim.x;
        if (t >= ntiles) break;
        m0 = (t % ntm) * TM; n0 = (t / ntm) * TN;
    }

    // ---- one reduction + atomic pair per CTA ----
    #pragma unroll
    for (int o = 16; o; o >>= 1) {
        s_base += __shfl_down_sync(0xFFFFFFFFu, s_base, o);
        s_g    += __shfl_down_sync(0xFFFFFFFFu, s_g, o);
    }
    double* red = reinterpret_cast<double*>(smem + SM_RED);
    if (lane == 0) { red[wid] = (double)s_base; red[8 + wid] = (double)s_g; }
    __syncthreads();
    if (tid == 0) {
        double tb = 0.0, tg = 0.0;
        #pragma unroll
        for (int w = 0; w < 8; ++w) { tb += red[w]; tg += red[8 + w]; }
        atomicAdd(&g_sum_base, tb);
        atomicAdd(&g_sum_gather, tg);
    }
}

// ---------------------------------------------------------------------------
// Finalize
// ---------------------------------------------------------------------------
__global__ void finalize_kernel(const float* __restrict__ attn_mask, int M,
                                float* __restrict__ out, long long loss_idx) {
    __shared__ float red[256];
    float s = 0.f;
    for (int i = threadIdx.x; i < M; i += 256) s += attn_mask[i];
    red[threadIdx.x] = s;
    __syncthreads();
    for (int o = 128; o; o >>= 1) {
        if (threadIdx.x < o) red[threadIdx.x] += red[threadIdx.x + o];
        __syncthreads();
    }
    if (threadIdx.x == 0) {
        double loss = (g_sum_base - g_sum_gather) / (double)red[0];
        out[loss_idx] = (float)loss;
    }
}

// ---------------------------------------------------------------------------
// kernel_launch
// ---------------------------------------------------------------------------
extern "C" void kernel_launch(void* const* d_in, const int* in_sizes, int n_in,
                              void* d_out, int out_size) {
    const float*     hidden = (const float*)d_in[0];
    const float*     W      = (const float*)d_in[1];
    const long long* labels = (const long long*)d_in[2];
    const float*     amask  = (const float*)d_in[3];
    float*           out    = (float*)d_out;

    const int M = in_sizes[2];              // B*T
    const int H = in_sizes[0] / M;
    const int V = in_sizes[1] / H;
    const long long LV = (long long)M * (long long)V;
    const int write_logits = ((long long)out_size >= LV) ? 1 : 0;

    cudaFuncSetAttribute(spel_gemm_kernel, cudaFuncAttributeMaxDynamicSharedMemorySize, SMEM_TOTAL);

    {
        __half* dW; cudaGetSymbolAddress((void**)&dW, g_Wh);
        __half* dA; cudaGetSymbolAddress((void**)&dA, g_Ah);
        int nW8 = in_sizes[1] / 8, nA8 = in_sizes[0] / 8;
        cvt_kernel<<<(nW8 + 255) / 256, 256>>>(W, dW, nW8);
        cvt_kernel<<<(nA8 + 255) / 256, 256>>>(hidden, dA, nA8);
    }

    zero_acc_kernel<<<1, 1>>>();

    const int ntm = (M + TM - 1) / TM;
    const int ntiles = ntm * ((V + TN - 1) / TN);
    static int nsm = 0;
    if (nsm == 0) {
        cudaDeviceGetAttribute(&nsm, cudaDevAttrMultiProcessorCount, 0);
        if (nsm <= 0) nsm = 148;
    }
    const int grid = (ntiles < nsm) ? ntiles : nsm;

    spel_gemm_kernel<<<grid, NTH, SMEM_TOTAL>>>(labels, amask, out, M, H, V,
                                                write_logits, ntiles, ntm);

    if ((long long)out_size != LV) {
        finalize_kernel<<<1, 256>>>(amask, M, out, (long long)out_size - 1);
    }
}

// round 12
// speedup vs baseline: 1.0015x; 1.0015x over previous
#include <cuda_runtime.h>
#include <cuda_fp16.h>
#include <stdint.h>

// ---------------------------------------------------------------------------
// Scratch for fp16-converted operands (W padded 256 rows for OOB-safe cp.async)
// ---------------------------------------------------------------------------
#define H_CAP 1024
#define V_CAP 50000
#define M_CAP 1024
__device__ __half g_Wh[(size_t)(V_CAP + 256) * H_CAP];   // ~100.5 MB
__device__ __half g_Ah[(size_t)M_CAP * H_CAP];           // 2 MB

// ---------------------------------------------------------------------------
// Tiling: CTA 128x256, 8 warps (2m x 4n), warp tile 64x64, 256 threads.
// KC=64 (one 64-col sub-tile, 128B rows, SW128). 4 smem stages, prefetch
// distance 2 chunks, CP_WAIT(1). Loader: 12 cp.async/thread/chunk as 4
// slices of 3, one per k-step — every slice has >= 2 chunks of lead time.
// ---------------------------------------------------------------------------
#define TM 128
#define TN 256
#define KC 64
#define NTH 256
#define NCH_K 16         // H/KC

#define SM_RED   0                      // 16 doubles
#define SM_PIPE  4096
#define ASTAGE   (TM * 128)             // 16384 B
#define BSTAGE   (TN * 128)             // 32768 B
#define STAGEB   (ASTAGE + BSTAGE)      // 49152 B
#define NSTAGES  4
#define SMEM_TOTAL (SM_PIPE + NSTAGES * STAGEB)   // 200704 B (1 CTA/SM)

// ---------------------------------------------------------------------------
// PTX helpers (sm_80-baseline features: safe under compute_103 virtual arch)
// ---------------------------------------------------------------------------
__device__ __forceinline__ uint32_t smem_u32(const void* p) {
    uint32_t a;
    asm("{ .reg .u64 t; cvta.to.shared.u64 t, %1; cvt.u32.u64 %0, t; }" : "=r"(a) : "l"(p));
    return a;
}
__device__ __forceinline__ void cp16(uint32_t dst, const void* src, uint32_t srcbytes) {
    asm volatile("cp.async.cg.shared.global [%0], [%1], 16, %2;"
                 :: "r"(dst), "l"(src), "r"(srcbytes));
}
#define CP_COMMIT() asm volatile("cp.async.commit_group;" ::: "memory")
#define CP_WAIT(n)  asm volatile("cp.async.wait_group %0;" :: "n"(n) : "memory")

__device__ __forceinline__ void ldsm_x4(uint32_t* r, uint32_t addr) {
    asm volatile("ldmatrix.sync.aligned.m8n8.x4.shared.b16 {%0,%1,%2,%3}, [%4];"
                 : "=r"(r[0]), "=r"(r[1]), "=r"(r[2]), "=r"(r[3]) : "r"(addr));
}
__device__ __forceinline__ void mma16816(float* c, const uint32_t* a, uint32_t b0, uint32_t b1) {
    asm volatile(
        "mma.sync.aligned.m16n8k16.row.col.f32.f16.f16.f32 "
        "{%0,%1,%2,%3}, {%4,%5,%6,%7}, {%8,%9}, {%0,%1,%2,%3};"
        : "+f"(c[0]), "+f"(c[1]), "+f"(c[2]), "+f"(c[3])
        : "r"(a[0]), "r"(a[1]), "r"(a[2]), "r"(a[3]), "r"(b0), "r"(b1));
}
__device__ __forceinline__ void stcs2(float* p, float x, float y) {
    asm volatile("st.global.cs.v2.f32 [%0], {%1, %2};" :: "l"(p), "f"(x), "f"(y) : "memory");
}

// log1p(t) on [0,1], |err| < 3e-8 (A&S 4.1.44) — FMA-pipe only
__device__ __forceinline__ float log1p_poly(float t) {
    float p = -0.0064535442f;
    p = fmaf(p, t,  0.0360884937f);
    p = fmaf(p, t, -0.0953293897f);
    p = fmaf(p, t,  0.1676540711f);
    p = fmaf(p, t, -0.2407338084f);
    p = fmaf(p, t,  0.3317990258f);
    p = fmaf(p, t, -0.4998741238f);
    p = fmaf(p, t,  0.9999964239f);
    return p * t;
}

// ---------------------------------------------------------------------------
// Global loss accumulators
// ---------------------------------------------------------------------------
__device__ double g_sum_base;
__device__ double g_sum_gather;

__global__ void zero_acc_kernel() { g_sum_base = 0.0; g_sum_gather = 0.0; }

// ---------------------------------------------------------------------------
// fp32 -> fp16 conversion (8 floats per thread)
// ---------------------------------------------------------------------------
__global__ void cvt_kernel(const float* __restrict__ s, __half* __restrict__ d, int n8) {
    int i = blockIdx.x * blockDim.x + threadIdx.x;
    if (i < n8) {
        float4 v0 = reinterpret_cast<const float4*>(s)[2 * i + 0];
        float4 v1 = reinterpret_cast<const float4*>(s)[2 * i + 1];
        __half2 h0 = __floats2half2_rn(v0.x, v0.y);
        __half2 h1 = __floats2half2_rn(v0.z, v0.w);
        __half2 h2 = __floats2half2_rn(v1.x, v1.y);
        __half2 h3 = __floats2half2_rn(v1.z, v1.w);
        __half2* dp = reinterpret_cast<__half2*>(d) + 4 * i;
        dp[0] = h0; dp[1] = h1; dp[2] = h2; dp[3] = h3;
    }
}

// ---------------------------------------------------------------------------
// Persistent fused GEMM + BCE-loss kernel
//   logits[M,V] = A[M,H] @ W[V,H]^T  (fp16 in, fp32 accumulate)
// ---------------------------------------------------------------------------
__global__ void __launch_bounds__(NTH, 1)
spel_gemm_kernel(const long long* __restrict__ labels,
                 const float* __restrict__ attn_mask,
                 float* __restrict__ out,
                 int M, int H, int V, int write_logits,
                 int ntiles, int ntm) {
    extern __shared__ char smem[];
    const uint32_t sbase = smem_u32(smem);
    const int tid  = threadIdx.x;
    const int wid  = tid >> 5;
    const int lane = tid & 31;
    const int warp_m = wid >> 2;          // 0..1
    const int warp_n = wid & 3;           // 0..3

    const __half* __restrict__ Ah = g_Ah;
    const __half* __restrict__ Wh = g_Wh;
    const size_t rstep = (size_t)32 * H;  // 32-row pointer stride

    int t = blockIdx.x;
    if (t >= ntiles) return;

    float acc[4][8][4];
    #pragma unroll
    for (int i = 0; i < 4; ++i)
        #pragma unroll
        for (int j = 0; j < 8; ++j)
            #pragma unroll
            for (int k = 0; k < 4; ++k) acc[i][j][k] = 0.f;

    // ---- loader geometry ----
    const int seg = tid & 7;
    const int r0  = tid >> 3;                               // 0..31
    const uint32_t maskR = ((uint32_t)r0 * 16u) & 0x70u;
    const uint32_t dstR  = (((uint32_t)(r0 * 128 + seg * 16)) ^ maskR);

    // one cp.async entry e (0..11): e<4 -> A (jj=e); else B (jj=e-4)
    auto load_entry = [&](uint32_t dA, const __half* pA, const __half* pB,
                          int n0c, int e) {
        if (e < 4) {
            cp16(dA + e * 4096u, pA + (size_t)e * rstep, 16u);
        } else {
            int jj = e - 4;
            int gn = n0c + r0 + jj * 32;
            cp16(dA + ASTAGE + jj * 4096u,
                 pB + (size_t)jj * rstep, (gn < V) ? 16u : 0u);
        }
    };

    // full chunk load (prologue only)
    auto load_chunk_full = [&](int st, int m0c, int n0c, int c) {
        const int k0 = c * KC;
        const uint32_t dA = sbase + SM_PIPE + st * STAGEB + dstR;
        const __half* pA = Ah + (size_t)(m0c + r0) * H + k0 + seg * 8;
        const __half* pB = Wh + (size_t)(n0c + r0) * H + k0 + seg * 8;
        #pragma unroll
        for (int e = 0; e < 12; ++e) load_entry(dA, pA, pB, n0c, e);
    };

    // ---- per-warp constant swizzled ldmatrix offsets ----
    const int a_row  = warp_m * 64 + (lane & 15);
    const int b_row0 = warp_n * 64 + (lane & 7) + ((lane & 16) ? 8 : 0);
    const uint32_t khiA2 = (lane & 16) ? 16u : 0u;
    const uint32_t khiB2 = (lane & 8)  ? 16u : 0u;
    uint32_t offA[4], offB[4];
    #pragma unroll
    for (int mt = 0; mt < 4; ++mt) {
        uint32_t R = (uint32_t)(a_row + mt * 16) * 128u;
        offA[mt] = R ^ ((R >> 3) & 0x70u) ^ khiA2;
    }
    #pragma unroll
    for (int h = 0; h < 4; ++h) {
        uint32_t R = (uint32_t)(b_row0 + h * 16) * 128u;
        offB[h] = R ^ ((R >> 3) & 0x70u) ^ khiB2;
    }

    // ---- persistent pipeline: prefetch distance 2 chunks, 4 stages ----
    int m0 = (t % ntm) * TM, n0 = (t / ntm) * TN;
    load_chunk_full(0, m0, n0, 0);
    CP_COMMIT();
    load_chunk_full(1, m0, n0, 1);
    CP_COMMIT();

    int stage = 0;                        // stage of current chunk
    float s_base = 0.f, s_g = 0.f;
    const int gq = lane >> 2;
    const int q  = (lane & 3) * 2;

    for (;;) {
        #pragma unroll 1
        for (int c = 0; c < NCH_K; ++c) {
            // prefetch chunk c+2 (may cross into next tile)
            int pc = c + 2, pm0 = m0, pn0 = n0;
            bool have = true;
            if (pc >= NCH_K) {
                int tn = t + gridDim.x;
                if (tn < ntiles) { pm0 = (tn % ntm) * TM; pn0 = (tn / ntm) * TN; pc -= NCH_K; }
                else have = false;
            }
            const int pstage = (stage + 2) & 3;
            const uint32_t dAn = sbase + SM_PIPE + pstage * STAGEB + dstR;
            const __half* pAn = Ah + (size_t)(pm0 + r0) * H + pc * KC + seg * 8;
            const __half* pBn = Wh + (size_t)(pn0 + r0) * H + pc * KC + seg * 8;

            CP_WAIT(1);           // chunk c complete (chunk c+1 may be in flight)
            __syncthreads();      // all warps done with chunk c-2's stage too

            const uint32_t sA = sbase + SM_PIPE + stage * STAGEB;
            const uint32_t sB = sA + ASTAGE;

            #pragma unroll
            for (int ks = 0; ks < KC / 16; ++ks) {
                // one slice of 3 entries per k-step; all have >=2 chunks lead
                if (have) {
                    #pragma unroll
                    for (int i = 0; i < 3; ++i)
                        load_entry(dAn, pAn, pBn, pn0, ks * 3 + i);
                }
                const uint32_t kx = (uint32_t)ks * 32u;
                uint32_t af[4][4], bf[4][4];
                #pragma unroll
                for (int mt = 0; mt < 4; ++mt) ldsm_x4(af[mt], sA + (offA[mt] ^ kx));
                #pragma unroll
                for (int h = 0; h < 4; ++h)    ldsm_x4(bf[h],  sB + (offB[h] ^ kx));
                #pragma unroll
                for (int mt = 0; mt < 4; ++mt) {
                    #pragma unroll
                    for (int nt = 0; nt < 8; ++nt) {
                        mma16816(acc[mt][nt], af[mt],
                                 bf[nt >> 1][(nt & 1) * 2 + 0],
                                 bf[nt >> 1][(nt & 1) * 2 + 1]);
                    }
                }
            }
            CP_COMMIT();          // empty group when !have — keeps accounting uniform
            stage = (stage + 1) & 3;
        }

        // ---- epilogue (no syncs; next tile's chunks 0-1 already in flight) ----
        // acc[] indices are all compile-time (dynamic would spill to local).
        {
            const int colbase = n0 + warp_n * 64;
            #pragma unroll
            for (int mt = 0; mt < 4; ++mt) {
                #pragma unroll
                for (int half = 0; half < 2; ++half) {
                    const int r = warp_m * 64 + mt * 16 + gq + half * 8;
                    const int gm = m0 + r;
                    if (gm < M) {
                        const float mk = attn_mask[gm];
                        const long long lb = labels[gm];
                        float* orow = out + (size_t)gm * V;
                        float rowsum = 0.f;
                        #pragma unroll
                        for (int nt = 0; nt < 8; ++nt) {
                            const int gn = colbase + nt * 8 + q;
                            if (gn < V) {
                                const float x0 = acc[mt][nt][half * 2 + 0];
                                const float x1 = acc[mt][nt][half * 2 + 1];
                                if (write_logits) stcs2(orow + gn, x0, x1);
                                rowsum += fmaxf(x0, 0.f) + log1p_poly(__expf(-fabsf(x0)));
                                rowsum += fmaxf(x1, 0.f) + log1p_poly(__expf(-fabsf(x1)));
                                if (mk > 0.f) {
                                    if (lb == (long long)gn)          s_g += x0 * mk;
                                    else if (lb == (long long)gn + 1) s_g += x1 * mk;
                                }
                            }
                        }
                        s_base += rowsum * mk;
                    }
                }
            }
            #pragma unroll
            for (int i = 0; i < 4; ++i)
                #pragma unroll
                for (int j = 0; j < 8; ++j)
                    #pragma unroll
                    for (int k = 0; k < 4; ++k) acc[i][j][k] = 0.f;
        }

        t += gridDim.x;
        if (t >= ntiles) break;
        m0 = (t % ntm) * TM; n0 = (t / ntm) * TN;
    }

    // ---- one reduction + atomic pair per CTA ----
    #pragma unroll
    for (int o = 16; o; o >>= 1) {
        s_base += __shfl_down_sync(0xFFFFFFFFu, s_base, o);
        s_g    += __shfl_down_sync(0xFFFFFFFFu, s_g, o);
    }
    double* red = reinterpret_cast<double*>(smem + SM_RED);
    if (lane == 0) { red[wid] = (double)s_base; red[8 + wid] = (double)s_g; }
    __syncthreads();
    if (tid == 0) {
        double tb = 0.0, tg = 0.0;
        #pragma unroll
        for (int w = 0; w < 8; ++w) { tb += red[w]; tg += red[8 + w]; }
        atomicAdd(&g_sum_base, tb);
        atomicAdd(&g_sum_gather, tg);
    }
}

// ---------------------------------------------------------------------------
// Finalize
// ---------------------------------------------------------------------------
__global__ void finalize_kernel(const float* __restrict__ attn_mask, int M,
                                float* __restrict__ out, long long loss_idx) {
    __shared__ float red[256];
    float s = 0.f;
    for (int i = threadIdx.x; i < M; i += 256) s += attn_mask[i];
    red[threadIdx.x] = s;
    __syncthreads();
    for (int o = 128; o; o >>= 1) {
        if (threadIdx.x < o) red[threadIdx.x] += red[threadIdx.x + o];
        __syncthreads();
    }
    if (threadIdx.x == 0) {
        double loss = (g_sum_base - g_sum_gather) / (double)red[0];
        out[loss_idx] = (float)loss;
    }
}

// ---------------------------------------------------------------------------
// kernel_launch
// ---------------------------------------------------------------------------
extern "C" void kernel_launch(void* const* d_in, const int* in_sizes, int n_in,
                              void* d_out, int out_size) {
    const float*     hidden = (const float*)d_in[0];
    const float*     W      = (const float*)d_in[1];
    const long long* labels = (const long long*)d_in[2];
    const float*     amask  = (const float*)d_in[3];
    float*           out    = (float*)d_out;

    const int M = in_sizes[2];              // B*T
    const int H = in_sizes[0] / M;
    const int V = in_sizes[1] / H;
    const long long LV = (long long)M * (long long)V;
    const int write_logits = ((long long)out_size >= LV) ? 1 : 0;

    cudaFuncSetAttribute(spel_gemm_kernel, cudaFuncAttributeMaxDynamicSharedMemorySize, SMEM_TOTAL);

    {
        __half* dW; cudaGetSymbolAddress((void**)&dW, g_Wh);
        __half* dA; cudaGetSymbolAddress((void**)&dA, g_Ah);
        int nW8 = in_sizes[1] / 8, nA8 = in_sizes[0] / 8;
        cvt_kernel<<<(nW8 + 255) / 256, 256>>>(W, dW, nW8);
        cvt_kernel<<<(nA8 + 255) / 256, 256>>>(hidden, dA, nA8);
    }

    zero_acc_kernel<<<1, 1>>>();

    const int ntm = (M + TM - 1) / TM;
    const int ntiles = ntm * ((V + TN - 1) / TN);
    static int nsm = 0;
    if (nsm == 0) {
        cudaDeviceGetAttribute(&nsm, cudaDevAttrMultiProcessorCount, 0);
        if (nsm <= 0) nsm = 148;
    }
    const int grid = (ntiles < nsm) ? ntiles : nsm;

    spel_gemm_kernel<<<grid, NTH, SMEM_TOTAL>>>(labels, amask, out, M, H, V,
                                                write_logits, ntiles, ntm);

    if ((long long)out_size != LV) {
        finalize_kernel<<<1, 256>>>(amask, M, out, (long long)out_size - 1);
    }
}

// round 13
// speedup vs baseline: 1.0385x; 1.0370x over previous
#include <cuda_runtime.h>
#include <cuda_fp16.h>
#include <stdint.h>

// ---------------------------------------------------------------------------
// Scratch for fp16-converted operands (W padded 256 rows for OOB-safe cp.async)
// ---------------------------------------------------------------------------
#define H_CAP 1024
#define V_CAP 50000
#define M_CAP 1024
__device__ __half g_Wh[(size_t)(V_CAP + 256) * H_CAP];   // ~100.5 MB
__device__ __half g_Ah[(size_t)M_CAP * H_CAP];           // 2 MB

// ---------------------------------------------------------------------------
// Tiling: CTA 128x256, 8 warps (2m x 4n), warp tile 64x64, 256 threads
// KC=128 as 2 sub-tiles of 64 cols (128B rows, SW128). Persistent CTAs.
// Loader strip-mined: 24 cp.async/thread/chunk issued as 6 slices of 4 on
// k-steps 1..6 — ks0 is left free for the post-barrier LDSM burst, and the
// last slice still has ~2 k-steps of lead before its CP_WAIT.
// ---------------------------------------------------------------------------
#define TM 128
#define TN 256
#define KC 128
#define NTH 256
#define NCH_K 8          // H/KC

#define SM_RED   0                      // 16 doubles
#define SM_PIPE  4096
#define ASUB     (TM * 128)             // 16384 B
#define BSUB     (TN * 128)             // 32768 B
#define ASTAGE   (2 * ASUB)             // 32768 B
#define BSTAGE   (2 * BSUB)             // 65536 B
#define STAGEB   (ASTAGE + BSTAGE)      // 98304 B
#define SMEM_TOTAL (SM_PIPE + 2 * STAGEB)   // 200704 B (1 CTA/SM)

// ---------------------------------------------------------------------------
// PTX helpers (sm_80-baseline features: safe under compute_103 virtual arch)
// ---------------------------------------------------------------------------
__device__ __forceinline__ uint32_t smem_u32(const void* p) {
    uint32_t a;
    asm("{ .reg .u64 t; cvta.to.shared.u64 t, %1; cvt.u32.u64 %0, t; }" : "=r"(a) : "l"(p));
    return a;
}
__device__ __forceinline__ void cp16(uint32_t dst, const void* src, uint32_t srcbytes) {
    asm volatile("cp.async.cg.shared.global [%0], [%1], 16, %2;"
                 :: "r"(dst), "l"(src), "r"(srcbytes));
}
#define CP_COMMIT() asm volatile("cp.async.commit_group;" ::: "memory")
#define CP_WAIT(n)  asm volatile("cp.async.wait_group %0;" :: "n"(n) : "memory")

__device__ __forceinline__ void ldsm_x4(uint32_t* r, uint32_t addr) {
    asm volatile("ldmatrix.sync.aligned.m8n8.x4.shared.b16 {%0,%1,%2,%3}, [%4];"
                 : "=r"(r[0]), "=r"(r[1]), "=r"(r[2]), "=r"(r[3]) : "r"(addr));
}
__device__ __forceinline__ void mma16816(float* c, const uint32_t* a, uint32_t b0, uint32_t b1) {
    asm volatile(
        "mma.sync.aligned.m16n8k16.row.col.f32.f16.f16.f32 "
        "{%0,%1,%2,%3}, {%4,%5,%6,%7}, {%8,%9}, {%0,%1,%2,%3};"
        : "+f"(c[0]), "+f"(c[1]), "+f"(c[2]), "+f"(c[3])
        : "r"(a[0]), "r"(a[1]), "r"(a[2]), "r"(a[3]), "r"(b0), "r"(b1));
}
__device__ __forceinline__ void stcs2(float* p, float x, float y) {
    asm volatile("st.global.cs.v2.f32 [%0], {%1, %2};" :: "l"(p), "f"(x), "f"(y) : "memory");
}

// log1p(t) on [0,1], |err| < 3e-8 (A&S 4.1.44) — FMA-pipe only
__device__ __forceinline__ float log1p_poly(float t) {
    float p = -0.0064535442f;
    p = fmaf(p, t,  0.0360884937f);
    p = fmaf(p, t, -0.0953293897f);
    p = fmaf(p, t,  0.1676540711f);
    p = fmaf(p, t, -0.2407338084f);
    p = fmaf(p, t,  0.3317990258f);
    p = fmaf(p, t, -0.4998741238f);
    p = fmaf(p, t,  0.9999964239f);
    return p * t;
}

// ---------------------------------------------------------------------------
// Global loss accumulators
// ---------------------------------------------------------------------------
__device__ double g_sum_base;
__device__ double g_sum_gather;

__global__ void zero_acc_kernel() { g_sum_base = 0.0; g_sum_gather = 0.0; }

// ---------------------------------------------------------------------------
// fp32 -> fp16 conversion (8 floats per thread)
// ---------------------------------------------------------------------------
__global__ void cvt_kernel(const float* __restrict__ s, __half* __restrict__ d, int n8) {
    int i = blockIdx.x * blockDim.x + threadIdx.x;
    if (i < n8) {
        float4 v0 = reinterpret_cast<const float4*>(s)[2 * i + 0];
        float4 v1 = reinterpret_cast<const float4*>(s)[2 * i + 1];
        __half2 h0 = __floats2half2_rn(v0.x, v0.y);
        __half2 h1 = __floats2half2_rn(v0.z, v0.w);
        __half2 h2 = __floats2half2_rn(v1.x, v1.y);
        __half2 h3 = __floats2half2_rn(v1.z, v1.w);
        __half2* dp = reinterpret_cast<__half2*>(d) + 4 * i;
        dp[0] = h0; dp[1] = h1; dp[2] = h2; dp[3] = h3;
    }
}

// ---------------------------------------------------------------------------
// Persistent fused GEMM + BCE-loss kernel
//   logits[M,V] = A[M,H] @ W[V,H]^T  (fp16 in, fp32 accumulate)
// ---------------------------------------------------------------------------
__global__ void __launch_bounds__(NTH, 1)
spel_gemm_kernel(const long long* __restrict__ labels,
                 const float* __restrict__ attn_mask,
                 float* __restrict__ out,
                 int M, int H, int V, int write_logits,
                 int ntiles, int ntm) {
    extern __shared__ char smem[];
    const uint32_t sbase = smem_u32(smem);
    const int tid  = threadIdx.x;
    const int wid  = tid >> 5;
    const int lane = tid & 31;
    const int warp_m = wid >> 2;          // 0..1
    const int warp_n = wid & 3;           // 0..3

    const __half* __restrict__ Ah = g_Ah;
    const __half* __restrict__ Wh = g_Wh;
    const size_t rstep = (size_t)32 * H;  // 32-row pointer stride

    int t = blockIdx.x;
    if (t >= ntiles) return;

    float acc[4][8][4];
    #pragma unroll
    for (int i = 0; i < 4; ++i)
        #pragma unroll
        for (int j = 0; j < 8; ++j)
            #pragma unroll
            for (int k = 0; k < 4; ++k) acc[i][j][k] = 0.f;

    // ---- loader geometry ----
    const int seg = tid & 7;
    const int r0  = tid >> 3;                               // 0..31
    const uint32_t maskR = ((uint32_t)r0 * 16u) & 0x70u;
    const uint32_t dstR  = (((uint32_t)(r0 * 128 + seg * 16)) ^ maskR);

    // one cp.async entry e (0..23): e<8 -> A (sub=e>>2, jj=e&3); else B (eb=e-8)
    auto load_entry = [&](uint32_t dA, const __half* pA, const __half* pB,
                          int n0c, int e) {
        if (e < 8) {
            int sub = e >> 2, jj = e & 3;
            cp16(dA + sub * ASUB + jj * 4096u,
                 pA + sub * 64 + (size_t)jj * rstep, 16u);
        } else {
            int eb = e - 8;
            int sub = eb >> 3, jj = eb & 7;
            int gn = n0c + r0 + jj * 32;
            cp16(dA + ASTAGE + sub * BSUB + jj * 4096u,
                 pB + sub * 64 + (size_t)jj * rstep, (gn < V) ? 16u : 0u);
        }
    };

    // full chunk load (prologue only)
    auto load_chunk_full = [&](int st, int m0c, int n0c, int c) {
        const int k0 = c * KC;
        const uint32_t dA = sbase + SM_PIPE + st * STAGEB + dstR;
        const __half* pA = Ah + (size_t)(m0c + r0) * H + k0 + seg * 8;
        const __half* pB = Wh + (size_t)(n0c + r0) * H + k0 + seg * 8;
        #pragma unroll
        for (int e = 0; e < 24; ++e) load_entry(dA, pA, pB, n0c, e);
    };

    // ---- per-warp constant swizzled ldmatrix offsets ----
    const int a_row  = warp_m * 64 + (lane & 15);
    const int b_row0 = warp_n * 64 + (lane & 7) + ((lane & 16) ? 8 : 0);
    const uint32_t khiA2 = (lane & 16) ? 16u : 0u;
    const uint32_t khiB2 = (lane & 8)  ? 16u : 0u;
    uint32_t offA[4], offB[4];
    #pragma unroll
    for (int mt = 0; mt < 4; ++mt) {
        uint32_t R = (uint32_t)(a_row + mt * 16) * 128u;
        offA[mt] = R ^ ((R >> 3) & 0x70u) ^ khiA2;
    }
    #pragma unroll
    for (int h = 0; h < 4; ++h) {
        uint32_t R = (uint32_t)(b_row0 + h * 16) * 128u;
        offB[h] = R ^ ((R >> 3) & 0x70u) ^ khiB2;
    }

    // ---- persistent pipeline over (tile, chunk) ----
    int m0 = (t % ntm) * TM, n0 = (t / ntm) * TN;
    load_chunk_full(0, m0, n0, 0);
    CP_COMMIT();
    int s = 0;
    float s_base = 0.f, s_g = 0.f;
    const int gq = lane >> 2;
    const int q  = (lane & 3) * 2;

    for (;;) {
        #pragma unroll 1
        for (int c = 0; c < NCH_K; ++c) {
            // next-chunk coordinates (cross-tile prefetch)
            int nm0 = m0, nn0 = n0, nc = c + 1;
            bool have_next = true;
            if (nc == NCH_K) {
                int tn = t + gridDim.x;
                if (tn < ntiles) { nm0 = (tn % ntm) * TM; nn0 = (tn / ntm) * TN; nc = 0; }
                else have_next = false;
            }
            const uint32_t dAn = sbase + SM_PIPE + (s ^ 1) * STAGEB + dstR;
            const __half* pAn = Ah + (size_t)(nm0 + r0) * H + nc * KC + seg * 8;
            const __half* pBn = Wh + (size_t)(nn0 + r0) * H + nc * KC + seg * 8;

            CP_WAIT(0);           // chunk c (committed last iteration) done
            __syncthreads();      // visible to all warps; stage s^1 free

            const uint32_t sA = sbase + SM_PIPE + s * STAGEB;
            const uint32_t sB = sA + ASTAGE;

            #pragma unroll
            for (int ks = 0; ks < KC / 16; ++ks) {
                // strip-mined loader: slices of 4 entries on ks = 1..6
                // (ks0 reserved for post-barrier LDSM burst; last slice
                //  keeps ~2 k-steps of lead before its CP_WAIT)
                if (ks >= 1 && ks <= 6 && have_next) {
                    #pragma unroll
                    for (int i = 0; i < 4; ++i)
                        load_entry(dAn, pAn, pBn, nn0, (ks - 1) * 4 + i);
                }
                const uint32_t kx = (uint32_t)(ks & 3) * 32u;
                const uint32_t aO = sA + (uint32_t)(ks >> 2) * ASUB;
                const uint32_t bO = sB + (uint32_t)(ks >> 2) * BSUB;
                uint32_t af[4][4], bf[4][4];
                #pragma unroll
                for (int mt = 0; mt < 4; ++mt) ldsm_x4(af[mt], aO + (offA[mt] ^ kx));
                #pragma unroll
                for (int h = 0; h < 4; ++h)    ldsm_x4(bf[h],  bO + (offB[h] ^ kx));
                #pragma unroll
                for (int mt = 0; mt < 4; ++mt) {
                    #pragma unroll
                    for (int nt = 0; nt < 8; ++nt) {
                        mma16816(acc[mt][nt], af[mt],
                                 bf[nt >> 1][(nt & 1) * 2 + 0],
                                 bf[nt >> 1][(nt & 1) * 2 + 1]);
                    }
                }
            }
            if (have_next) CP_COMMIT();
            s ^= 1;
        }

        // ---- epilogue (no syncs; overlaps next tile's in-flight loads) ----
        // acc[] indices are all compile-time (dynamic would spill to local).
        {
            const int colbase = n0 + warp_n * 64;
            #pragma unroll
            for (int mt = 0; mt < 4; ++mt) {
                #pragma unroll
                for (int half = 0; half < 2; ++half) {
                    const int r = warp_m * 64 + mt * 16 + gq + half * 8;
                    const int gm = m0 + r;
                    if (gm < M) {
                        const float mk = attn_mask[gm];
                        const long long lb = labels[gm];
                        float* orow = out + (size_t)gm * V;
                        float rowsum = 0.f;
                        #pragma unroll
                        for (int nt = 0; nt < 8; ++nt) {
                            const int gn = colbase + nt * 8 + q;
                            if (gn < V) {
                                const float x0 = acc[mt][nt][half * 2 + 0];
                                const float x1 = acc[mt][nt][half * 2 + 1];
                                if (write_logits) stcs2(orow + gn, x0, x1);
                                rowsum += fmaxf(x0, 0.f) + log1p_poly(__expf(-fabsf(x0)));
                                rowsum += fmaxf(x1, 0.f) + log1p_poly(__expf(-fabsf(x1)));
                                if (mk > 0.f) {
                                    if (lb == (long long)gn)          s_g += x0 * mk;
                                    else if (lb == (long long)gn + 1) s_g += x1 * mk;
                                }
                            }
                        }
                        s_base += rowsum * mk;
                    }
                }
            }
            #pragma unroll
            for (int i = 0; i < 4; ++i)
                #pragma unroll
                for (int j = 0; j < 8; ++j)
                    #pragma unroll
                    for (int k = 0; k < 4; ++k) acc[i][j][k] = 0.f;
        }

        t += gridDim.x;
        if (t >= ntiles) break;
        m0 = (t % ntm) * TM; n0 = (t / ntm) * TN;
    }

    // ---- one reduction + atomic pair per CTA ----
    #pragma unroll
    for (int o = 16; o; o >>= 1) {
        s_base += __shfl_down_sync(0xFFFFFFFFu, s_base, o);
        s_g    += __shfl_down_sync(0xFFFFFFFFu, s_g, o);
    }
    double* red = reinterpret_cast<double*>(smem + SM_RED);
    if (lane == 0) { red[wid] = (double)s_base; red[8 + wid] = (double)s_g; }
    __syncthreads();
    if (tid == 0) {
        double tb = 0.0, tg = 0.0;
        #pragma unroll
        for (int w = 0; w < 8; ++w) { tb += red[w]; tg += red[8 + w]; }
        atomicAdd(&g_sum_base, tb);
        atomicAdd(&g_sum_gather, tg);
    }
}

// ---------------------------------------------------------------------------
// Finalize
// ---------------------------------------------------------------------------
__global__ void finalize_kernel(const float* __restrict__ attn_mask, int M,
                                float* __restrict__ out, long long loss_idx) {
    __shared__ float red[256];
    float s = 0.f;
    for (int i = threadIdx.x; i < M; i += 256) s += attn_mask[i];
    red[threadIdx.x] = s;
    __syncthreads();
    for (int o = 128; o; o >>= 1) {
        if (threadIdx.x < o) red[threadIdx.x] += red[threadIdx.x + o];
        __syncthreads();
    }
    if (threadIdx.x == 0) {
        double loss = (g_sum_base - g_sum_gather) / (double)red[0];
        out[loss_idx] = (float)loss;
    }
}

// ---------------------------------------------------------------------------
// kernel_launch
// ---------------------------------------------------------------------------
extern "C" void kernel_launch(void* const* d_in, const int* in_sizes, int n_in,
                              void* d_out, int out_size) {
    const float*     hidden = (const float*)d_in[0];
    const float*     W      = (const float*)d_in[1];
    const long long* labels = (const long long*)d_in[2];
    const float*     amask  = (const float*)d_in[3];
    float*           out    = (float*)d_out;

    const int M = in_sizes[2];              // B*T
    const int H = in_sizes[0] / M;
    const int V = in_sizes[1] / H;
    const long long LV = (long long)M * (long long)V;
    const int write_logits = ((long long)out_size >= LV) ? 1 : 0;

    cudaFuncSetAttribute(spel_gemm_kernel, cudaFuncAttributeMaxDynamicSharedMemorySize, SMEM_TOTAL);

    {
        __half* dW; cudaGetSymbolAddress((void**)&dW, g_Wh);
        __half* dA; cudaGetSymbolAddress((void**)&dA, g_Ah);
        int nW8 = in_sizes[1] / 8, nA8 = in_sizes[0] / 8;
        cvt_kernel<<<(nW8 + 255) / 256, 256>>>(W, dW, nW8);
        cvt_kernel<<<(nA8 + 255) / 256, 256>>>(hidden, dA, nA8);
    }

    zero_acc_kernel<<<1, 1>>>();

    const int ntm = (M + TM - 1) / TM;
    const int ntiles = ntm * ((V + TN - 1) / TN);
    static int nsm = 0;
    if (nsm == 0) {
        cudaDeviceGetAttribute(&nsm, cudaDevAttrMultiProcessorCount, 0);
        if (nsm <= 0) nsm = 148;
    }
    const int grid = (ntiles < nsm) ? ntiles : nsm;

    spel_gemm_kernel<<<grid, NTH, SMEM_TOTAL>>>(labels, amask, out, M, H, V,
                                                write_logits, ntiles, ntm);

    if ((long long)out_size != LV) {
        finalize_kernel<<<1, 256>>>(amask, M, out, (long long)out_size - 1);
    }
}

// round 14
// speedup vs baseline: 1.0682x; 1.0285x over previous
#include <cuda_runtime.h>
#include <cuda_fp16.h>
#include <stdint.h>

// ---------------------------------------------------------------------------
// Scratch for fp16-converted operands (W padded 256 rows for OOB-safe cp.async)
// ---------------------------------------------------------------------------
#define H_CAP 1024
#define V_CAP 50000
#define M_CAP 1024
__device__ __half g_Wh[(size_t)(V_CAP + 256) * H_CAP];   // ~100.5 MB
__device__ __half g_Ah[(size_t)M_CAP * H_CAP];           // 2 MB

// ---------------------------------------------------------------------------
// Tiling: CTA 128x256, 8 warps (2m x 4n), warp tile 64x64, 256 threads
// KC=128 as 2 sub-tiles of 64 cols (128B rows, SW128). Persistent CTAs.
// Loader strip-mined: 24 cp.async/thread/chunk issued as 4 slices of 6 on
// k-steps 0..3 (measured optimum: small-early beats both one big burst and
// slices that extend late into the chunk).
// ---------------------------------------------------------------------------
#define TM 128
#define TN 256
#define KC 128
#define NTH 256
#define NCH_K 8          // H/KC

#define SM_RED   0                      // 16 doubles
#define SM_PIPE  4096
#define ASUB     (TM * 128)             // 16384 B
#define BSUB     (TN * 128)             // 32768 B
#define ASTAGE   (2 * ASUB)             // 32768 B
#define BSTAGE   (2 * BSUB)             // 65536 B
#define STAGEB   (ASTAGE + BSTAGE)      // 98304 B
#define SMEM_TOTAL (SM_PIPE + 2 * STAGEB)   // 200704 B (1 CTA/SM)

// ---------------------------------------------------------------------------
// PTX helpers (sm_80-baseline features: safe under compute_103 virtual arch)
// ---------------------------------------------------------------------------
__device__ __forceinline__ uint32_t smem_u32(const void* p) {
    uint32_t a;
    asm("{ .reg .u64 t; cvta.to.shared.u64 t, %1; cvt.u32.u64 %0, t; }" : "=r"(a) : "l"(p));
    return a;
}
__device__ __forceinline__ void cp16(uint32_t dst, const void* src, uint32_t srcbytes) {
    asm volatile("cp.async.cg.shared.global [%0], [%1], 16, %2;"
                 :: "r"(dst), "l"(src), "r"(srcbytes));
}
#define CP_COMMIT() asm volatile("cp.async.commit_group;" ::: "memory")
#define CP_WAIT(n)  asm volatile("cp.async.wait_group %0;" :: "n"(n) : "memory")

__device__ __forceinline__ void ldsm_x4(uint32_t* r, uint32_t addr) {
    asm volatile("ldmatrix.sync.aligned.m8n8.x4.shared.b16 {%0,%1,%2,%3}, [%4];"
                 : "=r"(r[0]), "=r"(r[1]), "=r"(r[2]), "=r"(r[3]) : "r"(addr));
}
__device__ __forceinline__ void mma16816(float* c, const uint32_t* a, uint32_t b0, uint32_t b1) {
    asm volatile(
        "mma.sync.aligned.m16n8k16.row.col.f32.f16.f16.f32 "
        "{%0,%1,%2,%3}, {%4,%5,%6,%7}, {%8,%9}, {%0,%1,%2,%3};"
        : "+f"(c[0]), "+f"(c[1]), "+f"(c[2]), "+f"(c[3])
        : "r"(a[0]), "r"(a[1]), "r"(a[2]), "r"(a[3]), "r"(b0), "r"(b1));
}
__device__ __forceinline__ void stcs2(float* p, float x, float y) {
    asm volatile("st.global.cs.v2.f32 [%0], {%1, %2};" :: "l"(p), "f"(x), "f"(y) : "memory");
}

// log1p(t) on [0,1], |err| < 3e-8 (A&S 4.1.44) — FMA-pipe only
__device__ __forceinline__ float log1p_poly(float t) {
    float p = -0.0064535442f;
    p = fmaf(p, t,  0.0360884937f);
    p = fmaf(p, t, -0.0953293897f);
    p = fmaf(p, t,  0.1676540711f);
    p = fmaf(p, t, -0.2407338084f);
    p = fmaf(p, t,  0.3317990258f);
    p = fmaf(p, t, -0.4998741238f);
    p = fmaf(p, t,  0.9999964239f);
    return p * t;
}

// ---------------------------------------------------------------------------
// Global loss accumulators
// ---------------------------------------------------------------------------
__device__ double g_sum_base;
__device__ double g_sum_gather;

// ---------------------------------------------------------------------------
// fp32 -> fp16 conversion (8 floats per thread); optionally zeroes the loss
// accumulators (folded into the A-conversion launch to save one kernel).
// ---------------------------------------------------------------------------
__global__ void cvt_kernel(const float* __restrict__ s, __half* __restrict__ d,
                           int n8, int do_zero) {
    int i = blockIdx.x * blockDim.x + threadIdx.x;
    if (do_zero && i == 0) { g_sum_base = 0.0; g_sum_gather = 0.0; }
    if (i < n8) {
        float4 v0 = reinterpret_cast<const float4*>(s)[2 * i + 0];
        float4 v1 = reinterpret_cast<const float4*>(s)[2 * i + 1];
        __half2 h0 = __floats2half2_rn(v0.x, v0.y);
        __half2 h1 = __floats2half2_rn(v0.z, v0.w);
        __half2 h2 = __floats2half2_rn(v1.x, v1.y);
        __half2 h3 = __floats2half2_rn(v1.z, v1.w);
        __half2* dp = reinterpret_cast<__half2*>(d) + 4 * i;
        dp[0] = h0; dp[1] = h1; dp[2] = h2; dp[3] = h3;
    }
}

// ---------------------------------------------------------------------------
// Persistent fused GEMM + BCE-loss kernel
//   logits[M,V] = A[M,H] @ W[V,H]^T  (fp16 in, fp32 accumulate)
// ---------------------------------------------------------------------------
__global__ void __launch_bounds__(NTH, 1)
spel_gemm_kernel(const long long* __restrict__ labels,
                 const float* __restrict__ attn_mask,
                 float* __restrict__ out,
                 int M, int H, int V, int write_logits,
                 int ntiles, int ntm) {
    extern __shared__ char smem[];
    const uint32_t sbase = smem_u32(smem);
    const int tid  = threadIdx.x;
    const int wid  = tid >> 5;
    const int lane = tid & 31;
    const int warp_m = wid >> 2;          // 0..1
    const int warp_n = wid & 3;           // 0..3

    const __half* __restrict__ Ah = g_Ah;
    const __half* __restrict__ Wh = g_Wh;
    const size_t rstep = (size_t)32 * H;  // 32-row pointer stride

    int t = blockIdx.x;
    if (t >= ntiles) return;

    float acc[4][8][4];
    #pragma unroll
    for (int i = 0; i < 4; ++i)
        #pragma unroll
        for (int j = 0; j < 8; ++j)
            #pragma unroll
            for (int k = 0; k < 4; ++k) acc[i][j][k] = 0.f;

    // ---- loader geometry ----
    const int seg = tid & 7;
    const int r0  = tid >> 3;                               // 0..31
    const uint32_t maskR = ((uint32_t)r0 * 16u) & 0x70u;
    const uint32_t dstR  = (((uint32_t)(r0 * 128 + seg * 16)) ^ maskR);

    // one cp.async entry e (0..23): e<8 -> A (sub=e>>2, jj=e&3); else B (eb=e-8)
    auto load_entry = [&](uint32_t dA, const __half* pA, const __half* pB,
                          int n0c, int e) {
        if (e < 8) {
            int sub = e >> 2, jj = e & 3;
            cp16(dA + sub * ASUB + jj * 4096u,
                 pA + sub * 64 + (size_t)jj * rstep, 16u);
        } else {
            int eb = e - 8;
            int sub = eb >> 3, jj = eb & 7;
            int gn = n0c + r0 + jj * 32;
            cp16(dA + ASTAGE + sub * BSUB + jj * 4096u,
                 pB + sub * 64 + (size_t)jj * rstep, (gn < V) ? 16u : 0u);
        }
    };

    // full chunk load (prologue only)
    auto load_chunk_full = [&](int st, int m0c, int n0c, int c) {
        const int k0 = c * KC;
        const uint32_t dA = sbase + SM_PIPE + st * STAGEB + dstR;
        const __half* pA = Ah + (size_t)(m0c + r0) * H + k0 + seg * 8;
        const __half* pB = Wh + (size_t)(n0c + r0) * H + k0 + seg * 8;
        #pragma unroll
        for (int e = 0; e < 24; ++e) load_entry(dA, pA, pB, n0c, e);
    };

    // ---- per-warp constant swizzled ldmatrix offsets ----
    const int a_row  = warp_m * 64 + (lane & 15);
    const int b_row0 = warp_n * 64 + (lane & 7) + ((lane & 16) ? 8 : 0);
    const uint32_t khiA2 = (lane & 16) ? 16u : 0u;
    const uint32_t khiB2 = (lane & 8)  ? 16u : 0u;
    uint32_t offA[4], offB[4];
    #pragma unroll
    for (int mt = 0; mt < 4; ++mt) {
        uint32_t R = (uint32_t)(a_row + mt * 16) * 128u;
        offA[mt] = R ^ ((R >> 3) & 0x70u) ^ khiA2;
    }
    #pragma unroll
    for (int h = 0; h < 4; ++h) {
        uint32_t R = (uint32_t)(b_row0 + h * 16) * 128u;
        offB[h] = R ^ ((R >> 3) & 0x70u) ^ khiB2;
    }

    // ---- persistent pipeline over (tile, chunk) ----
    int m0 = (t % ntm) * TM, n0 = (t / ntm) * TN;
    load_chunk_full(0, m0, n0, 0);
    CP_COMMIT();
    int s = 0;
    float s_base = 0.f, s_g = 0.f;
    const int gq = lane >> 2;
    const int q  = (lane & 3) * 2;

    for (;;) {
        #pragma unroll 1
        for (int c = 0; c < NCH_K; ++c) {
            // next-chunk coordinates (cross-tile prefetch)
            int nm0 = m0, nn0 = n0, nc = c + 1;
            bool have_next = true;
            if (nc == NCH_K) {
                int tn = t + gridDim.x;
                if (tn < ntiles) { nm0 = (tn % ntm) * TM; nn0 = (tn / ntm) * TN; nc = 0; }
                else have_next = false;
            }
            const uint32_t dAn = sbase + SM_PIPE + (s ^ 1) * STAGEB + dstR;
            const __half* pAn = Ah + (size_t)(nm0 + r0) * H + nc * KC + seg * 8;
            const __half* pBn = Wh + (size_t)(nn0 + r0) * H + nc * KC + seg * 8;

            CP_WAIT(0);           // chunk c (committed last iteration) done
            __syncthreads();      // visible to all warps; stage s^1 free

            const uint32_t sA = sbase + SM_PIPE + s * STAGEB;
            const uint32_t sB = sA + ASTAGE;

            #pragma unroll
            for (int ks = 0; ks < KC / 16; ++ks) {
                // strip-mined loader: slices of 6 entries on ks = 0..3
                // (measured optimum — all slices early, >=4 k-steps lead)
                if (ks < 4 && have_next) {
                    #pragma unroll
                    for (int i = 0; i < 6; ++i)
                        load_entry(dAn, pAn, pBn, nn0, ks * 6 + i);
                }
                const uint32_t kx = (uint32_t)(ks & 3) * 32u;
                const uint32_t aO = sA + (uint32_t)(ks >> 2) * ASUB;
                const uint32_t bO = sB + (uint32_t)(ks >> 2) * BSUB;
                uint32_t af[4][4], bf[4][4];
                #pragma unroll
                for (int mt = 0; mt < 4; ++mt) ldsm_x4(af[mt], aO + (offA[mt] ^ kx));
                #pragma unroll
                for (int h = 0; h < 4; ++h)    ldsm_x4(bf[h],  bO + (offB[h] ^ kx));
                #pragma unroll
                for (int mt = 0; mt < 4; ++mt) {
                    #pragma unroll
                    for (int nt = 0; nt < 8; ++nt) {
                        mma16816(acc[mt][nt], af[mt],
                                 bf[nt >> 1][(nt & 1) * 2 + 0],
                                 bf[nt >> 1][(nt & 1) * 2 + 1]);
                    }
                }
            }
            if (have_next) CP_COMMIT();
            s ^= 1;
        }

        // ---- epilogue (no syncs; overlaps next tile's in-flight loads) ----
        // acc[] indices are all compile-time (dynamic would spill to local).
        {
            const int colbase = n0 + warp_n * 64;
            #pragma unroll
            for (int mt = 0; mt < 4; ++mt) {
                #pragma unroll
                for (int half = 0; half < 2; ++half) {
                    const int r = warp_m * 64 + mt * 16 + gq + half * 8;
                    const int gm = m0 + r;
                    if (gm < M) {
                        const float mk = attn_mask[gm];
                        const long long lb = labels[gm];
                        float* orow = out + (size_t)gm * V;
                        float rowsum = 0.f;
                        #pragma unroll
                        for (int nt = 0; nt < 8; ++nt) {
                            const int gn = colbase + nt * 8 + q;
                            if (gn < V) {
                                const float x0 = acc[mt][nt][half * 2 + 0];
                                const float x1 = acc[mt][nt][half * 2 + 1];
                                if (write_logits) stcs2(orow + gn, x0, x1);
                                rowsum += fmaxf(x0, 0.f) + log1p_poly(__expf(-fabsf(x0)));
                                rowsum += fmaxf(x1, 0.f) + log1p_poly(__expf(-fabsf(x1)));
                                if (mk > 0.f) {
                                    if (lb == (long long)gn)          s_g += x0 * mk;
                                    else if (lb == (long long)gn + 1) s_g += x1 * mk;
                                }
                            }
                        }
                        s_base += rowsum * mk;
                    }
                }
            }
            #pragma unroll
            for (int i = 0; i < 4; ++i)
                #pragma unroll
                for (int j = 0; j < 8; ++j)
                    #pragma unroll
                    for (int k = 0; k < 4; ++k) acc[i][j][k] = 0.f;
        }

        t += gridDim.x;
        if (t >= ntiles) break;
        m0 = (t % ntm) * TM; n0 = (t / ntm) * TN;
    }

    // ---- one reduction + atomic pair per CTA ----
    #pragma unroll
    for (int o = 16; o; o >>= 1) {
        s_base += __shfl_down_sync(0xFFFFFFFFu, s_base, o);
        s_g    += __shfl_down_sync(0xFFFFFFFFu, s_g, o);
    }
    double* red = reinterpret_cast<double*>(smem + SM_RED);
    if (lane == 0) { red[wid] = (double)s_base; red[8 + wid] = (double)s_g; }
    __syncthreads();
    if (tid == 0) {
        double tb = 0.0, tg = 0.0;
        #pragma unroll
        for (int w = 0; w < 8; ++w) { tb += red[w]; tg += red[8 + w]; }
        atomicAdd(&g_sum_base, tb);
        atomicAdd(&g_sum_gather, tg);
    }
}

// ---------------------------------------------------------------------------
// Finalize
// ---------------------------------------------------------------------------
__global__ void finalize_kernel(const float* __restrict__ attn_mask, int M,
                                float* __restrict__ out, long long loss_idx) {
    __shared__ float red[256];
    float s = 0.f;
    for (int i = threadIdx.x; i < M; i += 256) s += attn_mask[i];
    red[threadIdx.x] = s;
    __syncthreads();
    for (int o = 128; o; o >>= 1) {
        if (threadIdx.x < o) red[threadIdx.x] += red[threadIdx.x + o];
        __syncthreads();
    }
    if (threadIdx.x == 0) {
        double loss = (g_sum_base - g_sum_gather) / (double)red[0];
        out[loss_idx] = (float)loss;
    }
}

// ---------------------------------------------------------------------------
// kernel_launch
// ---------------------------------------------------------------------------
extern "C" void kernel_launch(void* const* d_in, const int* in_sizes, int n_in,
                              void* d_out, int out_size) {
    const float*     hidden = (const float*)d_in[0];
    const float*     W      = (const float*)d_in[1];
    const long long* labels = (const long long*)d_in[2];
    const float*     amask  = (const float*)d_in[3];
    float*           out    = (float*)d_out;

    const int M = in_sizes[2];              // B*T
    const int H = in_sizes[0] / M;
    const int V = in_sizes[1] / H;
    const long long LV = (long long)M * (long long)V;
    const int write_logits = ((long long)out_size >= LV) ? 1 : 0;

    cudaFuncSetAttribute(spel_gemm_kernel, cudaFuncAttributeMaxDynamicSharedMemorySize, SMEM_TOTAL);

    {
        __half* dW; cudaGetSymbolAddress((void**)&dW, g_Wh);
        __half* dA; cudaGetSymbolAddress((void**)&dA, g_Ah);
        int nW8 = in_sizes[1] / 8, nA8 = in_sizes[0] / 8;
        cvt_kernel<<<(nA8 + 255) / 256, 256>>>(hidden, dA, nA8, 1);  // + zero accs
        cvt_kernel<<<(nW8 + 255) / 256, 256>>>(W, dW, nW8, 0);
    }

    const int ntm = (M + TM - 1) / TM;
    const int ntiles = ntm * ((V + TN - 1) / TN);
    static int nsm = 0;
    if (nsm == 0) {
        cudaDeviceGetAttribute(&nsm, cudaDevAttrMultiProcessorCount, 0);
        if (nsm <= 0) nsm = 148;
    }
    const int grid = (ntiles < nsm) ? ntiles : nsm;

    spel_gemm_kernel<<<grid, NTH, SMEM_TOTAL>>>(labels, amask, out, M, H, V,
                                                write_logits, ntiles, ntm);

    if ((long long)out_size != LV) {
        finalize_kernel<<<1, 256>>>(amask, M, out, (long long)out_size - 1);
    }
}

// round 15
// speedup vs baseline: 1.0764x; 1.0077x over previous
#include <cuda_runtime.h>
#include <cuda_fp16.h>
#include <stdint.h>

// ---------------------------------------------------------------------------
// Scratch for fp16-converted operands (W padded 256 rows for OOB-safe cp.async)
// ---------------------------------------------------------------------------
#define H_CAP 1024
#define V_CAP 50000
#define M_CAP 1024
__device__ __half g_Wh[(size_t)(V_CAP + 256) * H_CAP];   // ~100.5 MB
__device__ __half g_Ah[(size_t)M_CAP * H_CAP];           // 2 MB

// ---------------------------------------------------------------------------
// Tiling: CTA 128x256, 8 warps (2m x 4n), warp tile 64x64, 256 threads
// KC=128 as 2 sub-tiles of 64 cols (128B rows, SW128). Persistent CTAs.
// Loader strip-mined: 24 cp.async/thread/chunk as 4 slices of 6 on k-steps
// 0..3 (measured optimum). Loss finalize folded in via last-CTA pattern.
// ---------------------------------------------------------------------------
#define TM 128
#define TN 256
#define KC 128
#define NTH 256
#define NCH_K 8          // H/KC

#define SM_RED   0                      // 16 doubles
#define SM_PIPE  4096
#define ASUB     (TM * 128)             // 16384 B
#define BSUB     (TN * 128)             // 32768 B
#define ASTAGE   (2 * ASUB)             // 32768 B
#define BSTAGE   (2 * BSUB)             // 65536 B
#define STAGEB   (ASTAGE + BSTAGE)      // 98304 B
#define SMEM_TOTAL (SM_PIPE + 2 * STAGEB)   // 200704 B (1 CTA/SM)

// ---------------------------------------------------------------------------
// PTX helpers (sm_80-baseline features: safe under compute_103 virtual arch)
// ---------------------------------------------------------------------------
__device__ __forceinline__ uint32_t smem_u32(const void* p) {
    uint32_t a;
    asm("{ .reg .u64 t; cvta.to.shared.u64 t, %1; cvt.u32.u64 %0, t; }" : "=r"(a) : "l"(p));
    return a;
}
__device__ __forceinline__ void cp16(uint32_t dst, const void* src, uint32_t srcbytes) {
    asm volatile("cp.async.cg.shared.global [%0], [%1], 16, %2;"
                 :: "r"(dst), "l"(src), "r"(srcbytes));
}
#define CP_COMMIT() asm volatile("cp.async.commit_group;" ::: "memory")
#define CP_WAIT(n)  asm volatile("cp.async.wait_group %0;" :: "n"(n) : "memory")

__device__ __forceinline__ void ldsm_x4(uint32_t* r, uint32_t addr) {
    asm volatile("ldmatrix.sync.aligned.m8n8.x4.shared.b16 {%0,%1,%2,%3}, [%4];"
                 : "=r"(r[0]), "=r"(r[1]), "=r"(r[2]), "=r"(r[3]) : "r"(addr));
}
__device__ __forceinline__ void mma16816(float* c, const uint32_t* a, uint32_t b0, uint32_t b1) {
    asm volatile(
        "mma.sync.aligned.m16n8k16.row.col.f32.f16.f16.f32 "
        "{%0,%1,%2,%3}, {%4,%5,%6,%7}, {%8,%9}, {%0,%1,%2,%3};"
        : "+f"(c[0]), "+f"(c[1]), "+f"(c[2]), "+f"(c[3])
        : "r"(a[0]), "r"(a[1]), "r"(a[2]), "r"(a[3]), "r"(b0), "r"(b1));
}
__device__ __forceinline__ void stcs2(float* p, float x, float y) {
    asm volatile("st.global.cs.v2.f32 [%0], {%1, %2};" :: "l"(p), "f"(x), "f"(y) : "memory");
}

// log1p(t) on [0,1], |err| < 3e-8 (A&S 4.1.44) — FMA-pipe only
__device__ __forceinline__ float log1p_poly(float t) {
    float p = -0.0064535442f;
    p = fmaf(p, t,  0.0360884937f);
    p = fmaf(p, t, -0.0953293897f);
    p = fmaf(p, t,  0.1676540711f);
    p = fmaf(p, t, -0.2407338084f);
    p = fmaf(p, t,  0.3317990258f);
    p = fmaf(p, t, -0.4998741238f);
    p = fmaf(p, t,  0.9999964239f);
    return p * t;
}

// ---------------------------------------------------------------------------
// Global loss accumulators + completion counter (reset per launch by cvt)
// ---------------------------------------------------------------------------
__device__ double g_sum_base;
__device__ double g_sum_gather;
__device__ double g_mask_sum;
__device__ unsigned g_done;

// ---------------------------------------------------------------------------
// fp32 -> fp16 conversion (8 floats per thread); optionally zeroes the loss
// accumulators/counter. Source reads are evict-first (ld.cs) so the fp32
// stream does not flush the freshly-written fp16 data from L2.
// ---------------------------------------------------------------------------
__global__ void cvt_kernel(const float* __restrict__ s, __half* __restrict__ d,
                           int n8, int do_zero) {
    int i = blockIdx.x * blockDim.x + threadIdx.x;
    if (do_zero && i == 0) {
        g_sum_base = 0.0; g_sum_gather = 0.0; g_mask_sum = 0.0; g_done = 0u;
    }
    if (i < n8) {
        float4 v0 = __ldcs(reinterpret_cast<const float4*>(s) + 2 * i + 0);
        float4 v1 = __ldcs(reinterpret_cast<const float4*>(s) + 2 * i + 1);
        __half2 h0 = __floats2half2_rn(v0.x, v0.y);
        __half2 h1 = __floats2half2_rn(v0.z, v0.w);
        __half2 h2 = __floats2half2_rn(v1.x, v1.y);
        __half2 h3 = __floats2half2_rn(v1.z, v1.w);
        __half2* dp = reinterpret_cast<__half2*>(d) + 4 * i;
        dp[0] = h0; dp[1] = h1; dp[2] = h2; dp[3] = h3;
    }
}

// ---------------------------------------------------------------------------
// Persistent fused GEMM + BCE-loss kernel (self-finalizing)
//   logits[M,V] = A[M,H] @ W[V,H]^T  (fp16 in, fp32 accumulate)
// ---------------------------------------------------------------------------
__global__ void __launch_bounds__(NTH, 1)
spel_gemm_kernel(const long long* __restrict__ labels,
                 const float* __restrict__ attn_mask,
                 float* __restrict__ out,
                 int M, int H, int V, int write_logits,
                 int ntiles, int ntm,
                 int has_loss, long long loss_idx) {
    extern __shared__ char smem[];
    const uint32_t sbase = smem_u32(smem);
    const int tid  = threadIdx.x;
    const int wid  = tid >> 5;
    const int lane = tid & 31;
    const int warp_m = wid >> 2;          // 0..1
    const int warp_n = wid & 3;           // 0..3

    const __half* __restrict__ Ah = g_Ah;
    const __half* __restrict__ Wh = g_Wh;
    const size_t rstep = (size_t)32 * H;  // 32-row pointer stride

    double* red = reinterpret_cast<double*>(smem + SM_RED);

    // ---- CTA 0: mask-sum (tiny; overlaps pipeline fill of other CTAs) ----
    if (blockIdx.x == 0) {
        float sm = 0.f;
        for (int i = tid; i < M; i += NTH) sm += attn_mask[i];
        #pragma unroll
        for (int o = 16; o; o >>= 1) sm += __shfl_down_sync(0xFFFFFFFFu, sm, o);
        if (lane == 0) red[wid] = (double)sm;
        __syncthreads();
        if (tid == 0) {
            double tot = 0.0;
            #pragma unroll
            for (int w = 0; w < 8; ++w) tot += red[w];
            g_mask_sum = tot;
        }
        __syncthreads();
    }

    int t = blockIdx.x;
    // every CTA (even idle ones) must hit the completion counter at the end
    float acc[4][8][4];
    #pragma unroll
    for (int i = 0; i < 4; ++i)
        #pragma unroll
        for (int j = 0; j < 8; ++j)
            #pragma unroll
            for (int k = 0; k < 4; ++k) acc[i][j][k] = 0.f;

    float s_base = 0.f, s_g = 0.f;

    if (t < ntiles) {
        // ---- loader geometry ----
        const int seg = tid & 7;
        const int r0  = tid >> 3;                               // 0..31
        const uint32_t maskR = ((uint32_t)r0 * 16u) & 0x70u;
        const uint32_t dstR  = (((uint32_t)(r0 * 128 + seg * 16)) ^ maskR);

        auto load_entry = [&](uint32_t dA, const __half* pA, const __half* pB,
                              int n0c, int e) {
            if (e < 8) {
                int sub = e >> 2, jj = e & 3;
                cp16(dA + sub * ASUB + jj * 4096u,
                     pA + sub * 64 + (size_t)jj * rstep, 16u);
            } else {
                int eb = e - 8;
                int sub = eb >> 3, jj = eb & 7;
                int gn = n0c + r0 + jj * 32;
                cp16(dA + ASTAGE + sub * BSUB + jj * 4096u,
                     pB + sub * 64 + (size_t)jj * rstep, (gn < V) ? 16u : 0u);
            }
        };
        auto load_chunk_full = [&](int st, int m0c, int n0c, int c) {
            const int k0 = c * KC;
            const uint32_t dA = sbase + SM_PIPE + st * STAGEB + dstR;
            const __half* pA = Ah + (size_t)(m0c + r0) * H + k0 + seg * 8;
            const __half* pB = Wh + (size_t)(n0c + r0) * H + k0 + seg * 8;
            #pragma unroll
            for (int e = 0; e < 24; ++e) load_entry(dA, pA, pB, n0c, e);
        };

        // ---- per-warp constant swizzled ldmatrix offsets ----
        const int a_row  = warp_m * 64 + (lane & 15);
        const int b_row0 = warp_n * 64 + (lane & 7) + ((lane & 16) ? 8 : 0);
        const uint32_t khiA2 = (lane & 16) ? 16u : 0u;
        const uint32_t khiB2 = (lane & 8)  ? 16u : 0u;
        uint32_t offA[4], offB[4];
        #pragma unroll
        for (int mt = 0; mt < 4; ++mt) {
            uint32_t R = (uint32_t)(a_row + mt * 16) * 128u;
            offA[mt] = R ^ ((R >> 3) & 0x70u) ^ khiA2;
        }
        #pragma unroll
        for (int h = 0; h < 4; ++h) {
            uint32_t R = (uint32_t)(b_row0 + h * 16) * 128u;
            offB[h] = R ^ ((R >> 3) & 0x70u) ^ khiB2;
        }

        // ---- persistent pipeline over (tile, chunk) ----
        int m0 = (t % ntm) * TM, n0 = (t / ntm) * TN;
        load_chunk_full(0, m0, n0, 0);
        CP_COMMIT();
        int s = 0;
        const int gq = lane >> 2;
        const int q  = (lane & 3) * 2;

        for (;;) {
            #pragma unroll 1
            for (int c = 0; c < NCH_K; ++c) {
                int nm0 = m0, nn0 = n0, nc = c + 1;
                bool have_next = true;
                if (nc == NCH_K) {
                    int tn = t + gridDim.x;
                    if (tn < ntiles) { nm0 = (tn % ntm) * TM; nn0 = (tn / ntm) * TN; nc = 0; }
                    else have_next = false;
                }
                const uint32_t dAn = sbase + SM_PIPE + (s ^ 1) * STAGEB + dstR;
                const __half* pAn = Ah + (size_t)(nm0 + r0) * H + nc * KC + seg * 8;
                const __half* pBn = Wh + (size_t)(nn0 + r0) * H + nc * KC + seg * 8;

                CP_WAIT(0);
                __syncthreads();

                const uint32_t sA = sbase + SM_PIPE + s * STAGEB;
                const uint32_t sB = sA + ASTAGE;

                #pragma unroll
                for (int ks = 0; ks < KC / 16; ++ks) {
                    if (ks < 4 && have_next) {
                        #pragma unroll
                        for (int i = 0; i < 6; ++i)
                            load_entry(dAn, pAn, pBn, nn0, ks * 6 + i);
                    }
                    const uint32_t kx = (uint32_t)(ks & 3) * 32u;
                    const uint32_t aO = sA + (uint32_t)(ks >> 2) * ASUB;
                    const uint32_t bO = sB + (uint32_t)(ks >> 2) * BSUB;
                    uint32_t af[4][4], bf[4][4];
                    #pragma unroll
                    for (int mt = 0; mt < 4; ++mt) ldsm_x4(af[mt], aO + (offA[mt] ^ kx));
                    #pragma unroll
                    for (int h = 0; h < 4; ++h)    ldsm_x4(bf[h],  bO + (offB[h] ^ kx));
                    #pragma unroll
                    for (int mt = 0; mt < 4; ++mt) {
                        #pragma unroll
                        for (int nt = 0; nt < 8; ++nt) {
                            mma16816(acc[mt][nt], af[mt],
                                     bf[nt >> 1][(nt & 1) * 2 + 0],
                                     bf[nt >> 1][(nt & 1) * 2 + 1]);
                        }
                    }
                }
                if (have_next) CP_COMMIT();
                s ^= 1;
            }

            // ---- epilogue (no syncs; overlaps next tile's in-flight loads) ----
            {
                const int colbase = n0 + warp_n * 64;
                #pragma unroll
                for (int mt = 0; mt < 4; ++mt) {
                    #pragma unroll
                    for (int half = 0; half < 2; ++half) {
                        const int r = warp_m * 64 + mt * 16 + gq + half * 8;
                        const int gm = m0 + r;
                        if (gm < M) {
                            const float mk = attn_mask[gm];
                            const long long lb = labels[gm];
                            float* orow = out + (size_t)gm * V;
                            float rowsum = 0.f;
                            #pragma unroll
                            for (int nt = 0; nt < 8; ++nt) {
                                const int gn = colbase + nt * 8 + q;
                                if (gn < V) {
                                    const float x0 = acc[mt][nt][half * 2 + 0];
                                    const float x1 = acc[mt][nt][half * 2 + 1];
                                    if (write_logits) stcs2(orow + gn, x0, x1);
                                    rowsum += fmaxf(x0, 0.f) + log1p_poly(__expf(-fabsf(x0)));
                                    rowsum += fmaxf(x1, 0.f) + log1p_poly(__expf(-fabsf(x1)));
                                    if (mk > 0.f) {
                                        if (lb == (long long)gn)          s_g += x0 * mk;
                                        else if (lb == (long long)gn + 1) s_g += x1 * mk;
                                    }
                                }
                            }
                            s_base += rowsum * mk;
                        }
                    }
                }
                #pragma unroll
                for (int i = 0; i < 4; ++i)
                    #pragma unroll
                    for (int j = 0; j < 8; ++j)
                        #pragma unroll
                        for (int k = 0; k < 4; ++k) acc[i][j][k] = 0.f;
            }

            t += gridDim.x;
            if (t >= ntiles) break;
            m0 = (t % ntm) * TM; n0 = (t / ntm) * TN;
        }
    }

    // ---- per-CTA reduction + atomic pair, then last-CTA finalize ----
    #pragma unroll
    for (int o = 16; o; o >>= 1) {
        s_base += __shfl_down_sync(0xFFFFFFFFu, s_base, o);
        s_g    += __shfl_down_sync(0xFFFFFFFFu, s_g, o);
    }
    __syncthreads();   // red[] free (CTA0 used it earlier)
    if (lane == 0) { red[wid] = (double)s_base; red[8 + wid] = (double)s_g; }
    __syncthreads();
    if (tid == 0) {
        double tb = 0.0, tg = 0.0;
        #pragma unroll
        for (int w = 0; w < 8; ++w) { tb += red[w]; tg += red[8 + w]; }
        atomicAdd(&g_sum_base, tb);
        atomicAdd(&g_sum_gather, tg);
        __threadfence();
        unsigned rank = atomicAdd(&g_done, 1u);
        if (rank == gridDim.x - 1 && has_loss) {
            double sb = atomicAdd(&g_sum_base, 0.0);
            double sg = atomicAdd(&g_sum_gather, 0.0);
            out[loss_idx] = (float)((sb - sg) / g_mask_sum);
        }
    }
}

// ---------------------------------------------------------------------------
// kernel_launch
// ---------------------------------------------------------------------------
extern "C" void kernel_launch(void* const* d_in, const int* in_sizes, int n_in,
                              void* d_out, int out_size) {
    const float*     hidden = (const float*)d_in[0];
    const float*     W      = (const float*)d_in[1];
    const long long* labels = (const long long*)d_in[2];
    const float*     amask  = (const float*)d_in[3];
    float*           out    = (float*)d_out;

    const int M = in_sizes[2];              // B*T
    const int H = in_sizes[0] / M;
    const int V = in_sizes[1] / H;
    const long long LV = (long long)M * (long long)V;
    const int write_logits = ((long long)out_size >= LV) ? 1 : 0;
    const int has_loss = ((long long)out_size != LV) ? 1 : 0;

    cudaFuncSetAttribute(spel_gemm_kernel, cudaFuncAttributeMaxDynamicSharedMemorySize, SMEM_TOTAL);

    {
        __half* dW; cudaGetSymbolAddress((void**)&dW, g_Wh);
        __half* dA; cudaGetSymbolAddress((void**)&dA, g_Ah);
        int nW8 = in_sizes[1] / 8, nA8 = in_sizes[0] / 8;
        cvt_kernel<<<(nA8 + 255) / 256, 256>>>(hidden, dA, nA8, 1);  // + zero accs
        cvt_kernel<<<(nW8 + 255) / 256, 256>>>(W, dW, nW8, 0);
    }

    const int ntm = (M + TM - 1) / TM;
    const int ntiles = ntm * ((V + TN - 1) / TN);
    static int nsm = 0;
    if (nsm == 0) {
        cudaDeviceGetAttribute(&nsm, cudaDevAttrMultiProcessorCount, 0);
        if (nsm <= 0) nsm = 148;
    }
    const int grid = (ntiles < nsm) ? ntiles : nsm;

    spel_gemm_kernel<<<grid, NTH, SMEM_TOTAL>>>(labels, amask, out, M, H, V,
                                                write_logits, ntiles, ntm,
                                                has_loss, (long long)out_size - 1);
}

// round 16
// speedup vs baseline: 1.0953x; 1.0175x over previous
#include <cuda_runtime.h>
#include <cuda_fp16.h>
#include <stdint.h>

// ---------------------------------------------------------------------------
// Scratch for fp16-converted operands (W padded 512 rows for OOB-safe cp.async)
// ---------------------------------------------------------------------------
#define H_CAP 1024
#define V_CAP 50000
#define M_CAP 1024
__device__ __half g_Wh[(size_t)(V_CAP + 512) * H_CAP];   // ~100.5 MB
__device__ __half g_Ah[(size_t)M_CAP * H_CAP];           // 2 MB

// ---------------------------------------------------------------------------
// Tiling: CTA 128x128, 4 warps (2m x 2n), warp tile 64x64, 128 threads,
// 2 CTAs/SM (co-resident CTAs cover each other's barrier/wait gaps).
// KC=64 (128B rows, SW128). 3 smem stages, prefetch distance 2, WAIT(1):
// every load slice has >= 1 full chunk of lead time. Persistent CTAs.
// ---------------------------------------------------------------------------
#define TM 128
#define TN 128
#define KC 64
#define NTH 128
#define NCH_K 16         // H/KC

#define SM_RED   0                      // 16 doubles
#define SM_PIPE  1024
#define ASTAGE   (TM * 128)             // 16384 B
#define BSTAGE   (TN * 128)             // 16384 B
#define STAGEB   (ASTAGE + BSTAGE)      // 32768 B
#define NSTAGES  3
#define SMEM_TOTAL (SM_PIPE + NSTAGES * STAGEB)   // 99328 B -> 2 CTAs/SM

// ---------------------------------------------------------------------------
// PTX helpers (sm_80-baseline features: safe under compute_103 virtual arch)
// ---------------------------------------------------------------------------
__device__ __forceinline__ uint32_t smem_u32(const void* p) {
    uint32_t a;
    asm("{ .reg .u64 t; cvta.to.shared.u64 t, %1; cvt.u32.u64 %0, t; }" : "=r"(a) : "l"(p));
    return a;
}
__device__ __forceinline__ void cp16(uint32_t dst, const void* src, uint32_t srcbytes) {
    asm volatile("cp.async.cg.shared.global [%0], [%1], 16, %2;"
                 :: "r"(dst), "l"(src), "r"(srcbytes));
}
#define CP_COMMIT() asm volatile("cp.async.commit_group;" ::: "memory")
#define CP_WAIT(n)  asm volatile("cp.async.wait_group %0;" :: "n"(n) : "memory")

__device__ __forceinline__ void ldsm_x4(uint32_t* r, uint32_t addr) {
    asm volatile("ldmatrix.sync.aligned.m8n8.x4.shared.b16 {%0,%1,%2,%3}, [%4];"
                 : "=r"(r[0]), "=r"(r[1]), "=r"(r[2]), "=r"(r[3]) : "r"(addr));
}
__device__ __forceinline__ void mma16816(float* c, const uint32_t* a, uint32_t b0, uint32_t b1) {
    asm volatile(
        "mma.sync.aligned.m16n8k16.row.col.f32.f16.f16.f32 "
        "{%0,%1,%2,%3}, {%4,%5,%6,%7}, {%8,%9}, {%0,%1,%2,%3};"
        : "+f"(c[0]), "+f"(c[1]), "+f"(c[2]), "+f"(c[3])
        : "r"(a[0]), "r"(a[1]), "r"(a[2]), "r"(a[3]), "r"(b0), "r"(b1));
}
__device__ __forceinline__ void stcs2(float* p, float x, float y) {
    asm volatile("st.global.cs.v2.f32 [%0], {%1, %2};" :: "l"(p), "f"(x), "f"(y) : "memory");
}

// log1p(t) on [0,1], |err| < 3e-8 (A&S 4.1.44) — FMA-pipe only
__device__ __forceinline__ float log1p_poly(float t) {
    float p = -0.0064535442f;
    p = fmaf(p, t,  0.0360884937f);
    p = fmaf(p, t, -0.0953293897f);
    p = fmaf(p, t,  0.1676540711f);
    p = fmaf(p, t, -0.2407338084f);
    p = fmaf(p, t,  0.3317990258f);
    p = fmaf(p, t, -0.4998741238f);
    p = fmaf(p, t,  0.9999964239f);
    return p * t;
}

// ---------------------------------------------------------------------------
// Global loss accumulators + completion counter (reset per launch by cvt)
// ---------------------------------------------------------------------------
__device__ double g_sum_base;
__device__ double g_sum_gather;
__device__ double g_mask_sum;
__device__ unsigned g_done;

// ---------------------------------------------------------------------------
// fp32 -> fp16 conversion (8 floats per thread); ld.cs on source stream.
// ---------------------------------------------------------------------------
__global__ void cvt_kernel(const float* __restrict__ s, __half* __restrict__ d,
                           int n8, int do_zero) {
    int i = blockIdx.x * blockDim.x + threadIdx.x;
    if (do_zero && i == 0) {
        g_sum_base = 0.0; g_sum_gather = 0.0; g_mask_sum = 0.0; g_done = 0u;
    }
    if (i < n8) {
        float4 v0 = __ldcs(reinterpret_cast<const float4*>(s) + 2 * i + 0);
        float4 v1 = __ldcs(reinterpret_cast<const float4*>(s) + 2 * i + 1);
        __half2 h0 = __floats2half2_rn(v0.x, v0.y);
        __half2 h1 = __floats2half2_rn(v0.z, v0.w);
        __half2 h2 = __floats2half2_rn(v1.x, v1.y);
        __half2 h3 = __floats2half2_rn(v1.z, v1.w);
        __half2* dp = reinterpret_cast<__half2*>(d) + 4 * i;
        dp[0] = h0; dp[1] = h1; dp[2] = h2; dp[3] = h3;
    }
}

// ---------------------------------------------------------------------------
// Persistent fused GEMM + BCE-loss kernel (self-finalizing)
//   logits[M,V] = A[M,H] @ W[V,H]^T  (fp16 in, fp32 accumulate)
// ---------------------------------------------------------------------------
__global__ void __launch_bounds__(NTH, 2)
spel_gemm_kernel(const long long* __restrict__ labels,
                 const float* __restrict__ attn_mask,
                 float* __restrict__ out,
                 int M, int H, int V, int write_logits,
                 int ntiles, int ntm,
                 int has_loss, long long loss_idx) {
    extern __shared__ char smem[];
    const uint32_t sbase = smem_u32(smem);
    const int tid  = threadIdx.x;
    const int wid  = tid >> 5;
    const int lane = tid & 31;
    const int warp_m = wid >> 1;          // 0..1 (64 rows)
    const int warp_n = wid & 1;           // 0..1 (64 cols)

    const __half* __restrict__ Ah = g_Ah;
    const __half* __restrict__ Wh = g_Wh;
    const size_t rstep16 = (size_t)16 * H;   // 16-row pointer stride

    double* red = reinterpret_cast<double*>(smem + SM_RED);

    // ---- CTA 0: mask-sum (tiny; overlaps other CTAs' pipeline fill) ----
    if (blockIdx.x == 0) {
        float sm = 0.f;
        for (int i = tid; i < M; i += NTH) sm += attn_mask[i];
        #pragma unroll
        for (int o = 16; o; o >>= 1) sm += __shfl_down_sync(0xFFFFFFFFu, sm, o);
        if (lane == 0) red[wid] = (double)sm;
        __syncthreads();
        if (tid == 0) {
            double tot = red[0] + red[1] + red[2] + red[3];
            g_mask_sum = tot;
        }
        __syncthreads();
    }

    int t = blockIdx.x;
    float acc[4][8][4];
    #pragma unroll
    for (int i = 0; i < 4; ++i)
        #pragma unroll
        for (int j = 0; j < 8; ++j)
            #pragma unroll
            for (int k = 0; k < 4; ++k) acc[i][j][k] = 0.f;

    float s_base = 0.f, s_g = 0.f;

    if (t < ntiles) {
        // ---- loader geometry: 128 threads, seg 0..7, r0 0..15 ----
        const int seg = tid & 7;
        const int r0  = tid >> 3;
        const uint32_t maskR = ((uint32_t)r0 * 16u) & 0x70u;
        const uint32_t dstR  = (((uint32_t)(r0 * 128 + seg * 16)) ^ maskR);

        // one cp.async entry e (0..15): e<8 -> A (jj=e); else B (jj=e-8)
        auto load_entry = [&](uint32_t dA, const __half* pA, const __half* pB,
                              int n0c, int e) {
            if (e < 8) {
                cp16(dA + e * 2048u, pA + (size_t)e * rstep16, 16u);
            } else {
                int jj = e - 8;
                int gn = n0c + r0 + jj * 16;
                cp16(dA + ASTAGE + jj * 2048u,
                     pB + (size_t)jj * rstep16, (gn < V) ? 16u : 0u);
            }
        };
        auto load_chunk_full = [&](int st, int m0c, int n0c, int c) {
            const int k0 = c * KC;
            const uint32_t dA = sbase + SM_PIPE + st * STAGEB + dstR;
            const __half* pA = Ah + (size_t)(m0c + r0) * H + k0 + seg * 8;
            const __half* pB = Wh + (size_t)(n0c + r0) * H + k0 + seg * 8;
            #pragma unroll
            for (int e = 0; e < 16; ++e) load_entry(dA, pA, pB, n0c, e);
        };

        // ---- per-warp constant swizzled ldmatrix offsets ----
        const int a_row  = warp_m * 64 + (lane & 15);
        const int b_row0 = warp_n * 64 + (lane & 7) + ((lane & 16) ? 8 : 0);
        const uint32_t khiA2 = (lane & 16) ? 16u : 0u;
        const uint32_t khiB2 = (lane & 8)  ? 16u : 0u;
        uint32_t offA[4], offB[4];
        #pragma unroll
        for (int mt = 0; mt < 4; ++mt) {
            uint32_t R = (uint32_t)(a_row + mt * 16) * 128u;
            offA[mt] = R ^ ((R >> 3) & 0x70u) ^ khiA2;
        }
        #pragma unroll
        for (int h = 0; h < 4; ++h) {
            uint32_t R = (uint32_t)(b_row0 + h * 16) * 128u;
            offB[h] = R ^ ((R >> 3) & 0x70u) ^ khiB2;
        }

        // ---- pipeline: 3 stages, prefetch distance 2, WAIT(1) ----
        int m0 = (t % ntm) * TM, n0 = (t / ntm) * TN;
        load_chunk_full(0, m0, n0, 0);
        CP_COMMIT();
        load_chunk_full(1, m0, n0, 1);
        CP_COMMIT();

        int stage = 0;
        const int gq = lane >> 2;
        const int q  = (lane & 3) * 2;

        for (;;) {
            #pragma unroll 1
            for (int c = 0; c < NCH_K; ++c) {
                // prefetch chunk c+2 (may cross into next tile)
                int pc = c + 2, pm0 = m0, pn0 = n0;
                bool have = true;
                if (pc >= NCH_K) {
                    int tn = t + gridDim.x;
                    if (tn < ntiles) { pm0 = (tn % ntm) * TM; pn0 = (tn / ntm) * TN; pc -= NCH_K; }
                    else have = false;
                }
                int pstage = stage + 2; if (pstage >= NSTAGES) pstage -= NSTAGES;
                const uint32_t dAn = sbase + SM_PIPE + pstage * STAGEB + dstR;
                const __half* pAn = Ah + (size_t)(pm0 + r0) * H + pc * KC + seg * 8;
                const __half* pBn = Wh + (size_t)(pn0 + r0) * H + pc * KC + seg * 8;

                CP_WAIT(1);           // chunk c landed (c+1 still in flight)
                __syncthreads();      // all warps done with pstage's old data

                const uint32_t sA = sbase + SM_PIPE + stage * STAGEB;
                const uint32_t sB = sA + ASTAGE;

                #pragma unroll
                for (int ks = 0; ks < KC / 16; ++ks) {
                    // 4 slices of 4 entries — every slice >=1 chunk of lead
                    if (have) {
                        #pragma unroll
                        for (int i = 0; i < 4; ++i)
                            load_entry(dAn, pAn, pBn, pn0, ks * 4 + i);
                    }
                    const uint32_t kx = (uint32_t)ks * 32u;
                    uint32_t af[4][4], bf[4][4];
                    #pragma unroll
                    for (int mt = 0; mt < 4; ++mt) ldsm_x4(af[mt], sA + (offA[mt] ^ kx));
                    #pragma unroll
                    for (int h = 0; h < 4; ++h)    ldsm_x4(bf[h],  sB + (offB[h] ^ kx));
                    #pragma unroll
                    for (int mt = 0; mt < 4; ++mt) {
                        #pragma unroll
                        for (int nt = 0; nt < 8; ++nt) {
                            mma16816(acc[mt][nt], af[mt],
                                     bf[nt >> 1][(nt & 1) * 2 + 0],
                                     bf[nt >> 1][(nt & 1) * 2 + 1]);
                        }
                    }
                }
                CP_COMMIT();          // empty group when !have (uniform accounting)
                if (++stage == NSTAGES) stage = 0;
            }

            // ---- epilogue (no syncs; next tile's chunks already in flight) ----
            // acc[] indices are compile-time only (dynamic would spill).
            {
                const int colbase = n0 + warp_n * 64;
                #pragma unroll
                for (int mt = 0; mt < 4; ++mt) {
                    #pragma unroll
                    for (int half = 0; half < 2; ++half) {
                        const int r = warp_m * 64 + mt * 16 + gq + half * 8;
                        const int gm = m0 + r;
                        if (gm < M) {
                            const float mk = attn_mask[gm];
                            const long long lb = labels[gm];
                            float* orow = out + (size_t)gm * V;
                            float rowsum = 0.f;
                            #pragma unroll
                            for (int nt = 0; nt < 8; ++nt) {
                                const int gn = colbase + nt * 8 + q;
                                if (gn < V) {
                                    const float x0 = acc[mt][nt][half * 2 + 0];
                                    const float x1 = acc[mt][nt][half * 2 + 1];
                                    if (write_logits) stcs2(orow + gn, x0, x1);
                                    rowsum += fmaxf(x0, 0.f) + log1p_poly(__expf(-fabsf(x0)));
                                    rowsum += fmaxf(x1, 0.f) + log1p_poly(__expf(-fabsf(x1)));
                                    if (mk > 0.f) {
                                        if (lb == (long long)gn)          s_g += x0 * mk;
                                        else if (lb == (long long)gn + 1) s_g += x1 * mk;
                                    }
                                }
                            }
                            s_base += rowsum * mk;
                        }
                    }
                }
                #pragma unroll
                for (int i = 0; i < 4; ++i)
                    #pragma unroll
                    for (int j = 0; j < 8; ++j)
                        #pragma unroll
                        for (int k = 0; k < 4; ++k) acc[i][j][k] = 0.f;
            }

            t += gridDim.x;
            if (t >= ntiles) break;
            m0 = (t % ntm) * TM; n0 = (t / ntm) * TN;
        }
    }

    // ---- per-CTA reduction + atomic pair, then last-CTA finalize ----
    #pragma unroll
    for (int o = 16; o; o >>= 1) {
        s_base += __shfl_down_sync(0xFFFFFFFFu, s_base, o);
        s_g    += __shfl_down_sync(0xFFFFFFFFu, s_g, o);
    }
    __syncthreads();
    if (lane == 0) { red[wid] = (double)s_base; red[4 + wid] = (double)s_g; }
    __syncthreads();
    if (tid == 0) {
        double tb = red[0] + red[1] + red[2] + red[3];
        double tg = red[4] + red[5] + red[6] + red[7];
        atomicAdd(&g_sum_base, tb);
        atomicAdd(&g_sum_gather, tg);
        __threadfence();
        unsigned rank = atomicAdd(&g_done, 1u);
        if (rank == gridDim.x - 1 && has_loss) {
            double sb = atomicAdd(&g_sum_base, 0.0);
            double sg = atomicAdd(&g_sum_gather, 0.0);
            out[loss_idx] = (float)((sb - sg) / g_mask_sum);
        }
    }
}

// ---------------------------------------------------------------------------
// kernel_launch
// ---------------------------------------------------------------------------
extern "C" void kernel_launch(void* const* d_in, const int* in_sizes, int n_in,
                              void* d_out, int out_size) {
    const float*     hidden = (const float*)d_in[0];
    const float*     W      = (const float*)d_in[1];
    const long long* labels = (const long long*)d_in[2];
    const float*     amask  = (const float*)d_in[3];
    float*           out    = (float*)d_out;

    const int M = in_sizes[2];              // B*T
    const int H = in_sizes[0] / M;
    const int V = in_sizes[1] / H;
    const long long LV = (long long)M * (long long)V;
    const int write_logits = ((long long)out_size >= LV) ? 1 : 0;
    const int has_loss = ((long long)out_size != LV) ? 1 : 0;

    cudaFuncSetAttribute(spel_gemm_kernel, cudaFuncAttributeMaxDynamicSharedMemorySize, SMEM_TOTAL);

    {
        __half* dW; cudaGetSymbolAddress((void**)&dW, g_Wh);
        __half* dA; cudaGetSymbolAddress((void**)&dA, g_Ah);
        int nW8 = in_sizes[1] / 8, nA8 = in_sizes[0] / 8;
        cvt_kernel<<<(nA8 + 255) / 256, 256>>>(hidden, dA, nA8, 1);  // + zero accs
        cvt_kernel<<<(nW8 + 255) / 256, 256>>>(W, dW, nW8, 0);
    }

    const int ntm = (M + TM - 1) / TM;
    const int ntiles = ntm * ((V + TN - 1) / TN);
    static int nsm = 0;
    if (nsm == 0) {
        cudaDeviceGetAttribute(&nsm, cudaDevAttrMultiProcessorCount, 0);
        if (nsm <= 0) nsm = 148;
    }
    int grid = 2 * nsm;
    if (grid > ntiles) grid = ntiles;

    spel_gemm_kernel<<<grid, NTH, SMEM_TOTAL>>>(labels, amask, out, M, H, V,
                                                write_logits, ntiles, ntm,
                                                has_loss, (long long)out_size - 1);
}